// round 1
// baseline (speedup 1.0000x reference)
#include <cuda_runtime.h>
#include <math.h>

#define NN    2048
#define BATCH 16
#define DEMB  10
#define CTOT  128            // C_IN + C_OUT
#define CO    64
#define BC    (BATCH*CTOT)   // 2048
#define BZ    (BATCH*CO)     // 1024
#define KC    (3*CTOT)       // 384
#define JG    (KC*CTOT)      // 49152
#define JU    (KC*CO)        // 24576

// ---------------- device scratch (no allocation allowed) ----------------
__device__ float g_S  [(size_t)NN*NN];
__device__ float g_IAS[(size_t)NN*BC];
__device__ float g_XG1[(size_t)NN*BC];
__device__ float g_XG2[(size_t)NN*BC];
__device__ float g_Z  [(size_t)NN*BZ];
__device__ float g_ZG1[(size_t)NN*BZ];
__device__ float g_ZG2[(size_t)NN*BZ];
__device__ float g_Wg [(size_t)NN*JG];   // 402 MB
__device__ float g_Wu [(size_t)NN*JU];   // 201 MB

// ---------------- helpers ----------------
__device__ __forceinline__ float warpMax(float v){
  #pragma unroll
  for(int o=16;o;o>>=1) v = fmaxf(v, __shfl_xor_sync(0xffffffffu, v, o));
  return v;
}
__device__ __forceinline__ float warpSum(float v){
  #pragma unroll
  for(int o=16;o;o>>=1) v += __shfl_xor_sync(0xffffffffu, v, o);
  return v;
}

// ---------------- K1: S = softmax(relu(E E^T)) row-wise ----------------
__global__ void __launch_bounds__(256) k_supports(const float* __restrict__ E){
  __shared__ float sh[8];
  __shared__ float bcast;
  int row = blockIdx.x, tid = threadIdx.x;
  float Er[DEMB];
  #pragma unroll
  for(int d=0; d<DEMB; d++) Er[d] = E[row*DEMB + d];
  float a[8], m = -1e30f;
  #pragma unroll
  for(int q=0; q<8; q++){
    int col = tid + q*256;
    const float* Ec = E + (size_t)col*DEMB;
    float s = 0.f;
    #pragma unroll
    for(int d=0; d<DEMB; d++) s += Er[d]*Ec[d];
    s = fmaxf(s, 0.f);
    a[q] = s; m = fmaxf(m, s);
  }
  m = warpMax(m);
  if((tid&31)==0) sh[tid>>5] = m;
  __syncthreads();
  if(tid<32){ float t = (tid<8)? sh[tid] : -1e30f; t = warpMax(t); if(tid==0) bcast = t; }
  __syncthreads();
  m = bcast;
  float ssum = 0.f;
  #pragma unroll
  for(int q=0; q<8; q++){ a[q] = expf(a[q]-m); ssum += a[q]; }
  ssum = warpSum(ssum);
  __syncthreads();                       // everyone has consumed bcast/sh
  if((tid&31)==0) sh[tid>>5] = ssum;
  __syncthreads();
  if(tid<32){ float t = (tid<8)? sh[tid] : 0.f; t = warpSum(t); if(tid==0) bcast = t; }
  __syncthreads();
  float inv = 1.f/bcast;
  #pragma unroll
  for(int q=0; q<8; q++) g_S[(size_t)row*NN + tid + q*256] = a[q]*inv;
}

// ---------------- K2: pack IAS[n, b*128+c] = concat(x,state) ----------------
__global__ void __launch_bounds__(256) k_pack(const float* __restrict__ x,
                                              const float* __restrict__ st){
  int t = blockIdx.x*256 + threadIdx.x;       // 0 .. NN*BC/4-1
  int e = t*4;
  int n = e >> 11;
  int r = e & 2047;
  int b = r >> 7;
  int c = r & 127;
  float4 v;
  if (c < 64) v = *(const float4*)(x  + ((size_t)b*NN + n)*64 + c);
  else        v = *(const float4*)(st + ((size_t)b*NN + n)*64 + (c-64));
  *(float4*)(g_IAS + e) = v;
}

// ---------------- K5: W[n,j] = sum_d E[n,d] * wp[d,j] ----------------
__global__ void __launch_bounds__(256) k_wcombine(const float* __restrict__ E,
                                                  const float* __restrict__ wp,
                                                  int J, int which){
  float* out = which ? g_Wu : g_Wg;
  int j  = blockIdx.x*256 + threadIdx.x;
  int n0 = blockIdx.y*32;
  float w[DEMB];
  #pragma unroll
  for(int d=0; d<DEMB; d++) w[d] = wp[(size_t)d*J + j];
  __shared__ float Es[32*DEMB];
  for(int t=threadIdx.x; t<32*DEMB; t+=256) Es[t] = E[n0*DEMB + t];
  __syncthreads();
  #pragma unroll 4
  for(int nn=0; nn<32; nn++){
    float acc = 0.f;
    #pragma unroll
    for(int d=0; d<DEMB; d++) acc += Es[nn*DEMB+d]*w[d];
    out[(size_t)(n0+nn)*J + j] = acc;
  }
}

// ---------------- K3/K4/K7/K8: fp32 SGEMM C = S@B (MODE0) or C = 2*S@B - D (MODE1) ----
__device__ __forceinline__ const float* pickIn(int id){
  switch(id){ case 0: return g_IAS; case 1: return g_XG1;
              case 3: return g_Z;   case 4: return g_ZG1; }
  return g_IAS;
}
__device__ __forceinline__ float* pickOut(int id){
  switch(id){ case 1: return g_XG1; case 2: return g_XG2;
              case 4: return g_ZG1; case 5: return g_ZG2; }
  return g_XG1;
}

template<int MODE>
__global__ void __launch_bounds__(256) sgemm_k(int bId, int cId, int dId, int Ncols){
  const float* A = g_S;
  const float* B = pickIn(bId);
  float*       C = pickOut(cId);
  const float* D = pickIn(dId);

  __shared__ float As[8][128];
  __shared__ float Bs[8][128];
  int tid = threadIdx.x;
  int tx = tid & 15, ty = tid >> 4;
  int arow = tid >> 1,      acol = (tid & 1)*4;
  int brw  = tid >> 5,      bcl  = (tid & 31)*4;

  const float* Ap = A + (size_t)(blockIdx.y*128 + arow)*NN + acol;
  const float* Bp = B + (size_t)brw*Ncols + blockIdx.x*128 + bcl;

  float acc[8][8];
  #pragma unroll
  for(int m=0;m<8;m++)
    #pragma unroll
    for(int n=0;n<8;n++) acc[m][n]=0.f;

  for(int kk=0; kk<NN; kk+=8){
    float4 av = *(const float4*)(Ap + kk);
    float4 bv = *(const float4*)(Bp + (size_t)kk*Ncols);
    As[acol+0][arow]=av.x; As[acol+1][arow]=av.y;
    As[acol+2][arow]=av.z; As[acol+3][arow]=av.w;
    *(float4*)&Bs[brw][bcl] = bv;
    __syncthreads();
    #pragma unroll
    for(int k=0;k<8;k++){
      float ar[8], br[8];
      *(float4*)(ar)   = *(const float4*)&As[k][ty*8];
      *(float4*)(ar+4) = *(const float4*)&As[k][ty*8+4];
      *(float4*)(br)   = *(const float4*)&Bs[k][tx*8];
      *(float4*)(br+4) = *(const float4*)&Bs[k][tx*8+4];
      #pragma unroll
      for(int m=0;m<8;m++)
        #pragma unroll
        for(int n=0;n<8;n++) acc[m][n] += ar[m]*br[n];
    }
    __syncthreads();
  }
  #pragma unroll
  for(int m=0;m<8;m++){
    size_t row = (size_t)blockIdx.y*128 + ty*8 + m;
    size_t off = row*Ncols + blockIdx.x*128 + tx*8;
    #pragma unroll
    for(int n4=0;n4<8;n4+=4){
      float4 v;
      if (MODE==0){
        v.x=acc[m][n4]; v.y=acc[m][n4+1]; v.z=acc[m][n4+2]; v.w=acc[m][n4+3];
      } else {
        float4 dv = *(const float4*)(D + off + n4);
        v.x=2.f*acc[m][n4]  -dv.x; v.y=2.f*acc[m][n4+1]-dv.y;
        v.z=2.f*acc[m][n4+2]-dv.z; v.w=2.f*acc[m][n4+3]-dv.w;
      }
      *(float4*)(C + off + n4) = v;
    }
  }
}

// ---------------- K6: gate final: y = sigmoid(Xg@Wg + bg); Z = y@lin_w^T + lin_b ----
__global__ void __launch_bounds__(256) k_gate_final(const float* __restrict__ E,
                                                    const float* __restrict__ gbp,
                                                    const float* __restrict__ lw,
                                                    const float* __restrict__ lb){
  __shared__ float smA[128*65];        // phase2: Xs (6144 used); phase3: lwT (8320 used)
  __shared__ float ysig[BATCH*CTOT];   // 2048
  __shared__ float Es[DEMB];
  int n = blockIdx.x, tid = threadIdx.x;

  float* Xs = smA;
  for(int t=tid; t<512; t+=256){
    ((float4*)Xs)[t]        = ((const float4*)(g_IAS + (size_t)n*BC))[t];
    ((float4*)(Xs+2048))[t] = ((const float4*)(g_XG1 + (size_t)n*BC))[t];
    ((float4*)(Xs+4096))[t] = ((const float4*)(g_XG2 + (size_t)n*BC))[t];
  }
  if(tid<DEMB) Es[tid] = E[n*DEMB + tid];
  __syncthreads();

  int o  = tid & 127;
  int bg = tid >> 7;                   // 0..1 -> 8 batches each
  float bias = 0.f;
  #pragma unroll
  for(int d=0; d<DEMB; d++) bias += Es[d]*gbp[d*CTOT + o];
  float acc[8];
  #pragma unroll
  for(int bb=0; bb<8; bb++) acc[bb] = bias;

  const float* W = g_Wg + (size_t)n*JG + o;
  #pragma unroll 4
  for(int j=0; j<KC; j++){
    float w = W[(size_t)j*CTOT];
    int k = j >> 7, i = j & 127;
    const float* Xk = Xs + k*2048 + i;
    #pragma unroll
    for(int bb=0; bb<8; bb++) acc[bb] += w * Xk[(bg*8+bb)*CTOT];
  }
  #pragma unroll
  for(int bb=0; bb<8; bb++){
    float v = 1.f/(1.f + expf(-acc[bb]));
    ysig[(bg*8+bb)*CTOT + o] = v;
  }
  __syncthreads();                     // Xs dead; ysig ready

  float* lwT = smA;                    // lwT[o*65 + c]
  for(int t=tid; t<CO*CTOT; t+=256){ int c = t>>7, oo = t&127; lwT[oo*65 + c] = lw[t]; }
  __syncthreads();

  int c   = tid & 63;
  int bg2 = tid >> 6;                  // 0..3 -> 4 batches each
  float acc2[4];
  float lbv = lb[c];
  #pragma unroll
  for(int bb=0; bb<4; bb++) acc2[bb] = lbv;
  #pragma unroll 4
  for(int o2=0; o2<CTOT; o2++){
    float w = lwT[o2*65 + c];
    #pragma unroll
    for(int bb=0; bb<4; bb++) acc2[bb] += ysig[(bg2*4+bb)*CTOT + o2]*w;
  }
  #pragma unroll
  for(int bb=0; bb<4; bb++)
    g_Z[(size_t)n*BZ + (bg2*4+bb)*CO + c] = acc2[bb];
}

// ---------------- K9: upd final: out = tanh(Xc@Wu + bu) ----------------
__global__ void __launch_bounds__(256) k_upd_final(const float* __restrict__ E,
                                                   const float* __restrict__ ubp,
                                                   float* __restrict__ out){
  __shared__ float Xs[3*2048];
  __shared__ float Zs[3*1024];
  __shared__ float Es[DEMB];
  int n = blockIdx.x, tid = threadIdx.x;
  for(int t=tid; t<512; t+=256){
    ((float4*)Xs)[t]        = ((const float4*)(g_IAS + (size_t)n*BC))[t];
    ((float4*)(Xs+2048))[t] = ((const float4*)(g_XG1 + (size_t)n*BC))[t];
    ((float4*)(Xs+4096))[t] = ((const float4*)(g_XG2 + (size_t)n*BC))[t];
  }
  {
    int t = tid;
    if (t < 256){
      ((float4*)Zs)[t]        = ((const float4*)(g_Z   + (size_t)n*BZ))[t];
      ((float4*)(Zs+1024))[t] = ((const float4*)(g_ZG1 + (size_t)n*BZ))[t];
      ((float4*)(Zs+2048))[t] = ((const float4*)(g_ZG2 + (size_t)n*BZ))[t];
    }
  }
  if(tid<DEMB) Es[tid] = E[n*DEMB + tid];
  __syncthreads();

  int o  = tid & 63;
  int bg = tid >> 6;                   // 0..3 -> 4 batches each
  float bias = 0.f;
  #pragma unroll
  for(int d=0; d<DEMB; d++) bias += Es[d]*ubp[d*CO + o];
  float acc[4];
  #pragma unroll
  for(int bb=0; bb<4; bb++) acc[bb] = bias;

  const float* W = g_Wu + (size_t)n*JU + o;
  #pragma unroll
  for(int k=0; k<3; k++){
    #pragma unroll 4
    for(int i=0; i<64; i++){
      float w = W[(size_t)(k*128 + i)*CO];
      #pragma unroll
      for(int bb=0; bb<4; bb++) acc[bb] += w * Xs[k*2048 + (bg*4+bb)*CTOT + i];
    }
    #pragma unroll 4
    for(int i=0; i<64; i++){
      float w = W[(size_t)(k*128 + 64 + i)*CO];
      #pragma unroll
      for(int bb=0; bb<4; bb++) acc[bb] += w * Zs[k*1024 + (bg*4+bb)*CO + i];
    }
  }
  #pragma unroll
  for(int bb=0; bb<4; bb++)
    out[(size_t)(bg*4+bb)*((size_t)NN*CO) + (size_t)n*CO + o] = tanhf(acc[bb]);
}

// ---------------- launch ----------------
extern "C" void kernel_launch(void* const* d_in, const int* in_sizes, int n_in,
                              void* d_out, int out_size){
  (void)in_sizes; (void)n_in; (void)out_size;
  const float* x   = (const float*)d_in[0];
  const float* st  = (const float*)d_in[1];
  const float* E   = (const float*)d_in[2];
  const float* gwp = (const float*)d_in[3];
  const float* gbp = (const float*)d_in[4];
  const float* uwp = (const float*)d_in[5];
  const float* ubp = (const float*)d_in[6];
  const float* lw  = (const float*)d_in[7];
  const float* lb  = (const float*)d_in[8];
  float* out = (float*)d_out;

  k_supports<<<NN, 256>>>(E);
  k_pack<<<(NN*BC/4)/256, 256>>>(x, st);
  k_wcombine<<<dim3(JG/256, NN/32), 256>>>(E, gwp, JG, 0);
  k_wcombine<<<dim3(JU/256, NN/32), 256>>>(E, uwp, JU, 1);

  sgemm_k<0><<<dim3(BC/128, NN/128), 256>>>(0, 1, 0, BC);   // XG1 = S@IAS
  sgemm_k<1><<<dim3(BC/128, NN/128), 256>>>(1, 2, 0, BC);   // XG2 = 2*S@XG1 - IAS

  k_gate_final<<<NN, 256>>>(E, gbp, lw, lb);                // -> g_Z

  sgemm_k<0><<<dim3(BZ/128, NN/128), 256>>>(3, 4, 3, BZ);   // ZG1 = S@Z
  sgemm_k<1><<<dim3(BZ/128, NN/128), 256>>>(4, 5, 3, BZ);   // ZG2 = 2*S@ZG1 - Z

  k_upd_final<<<NN, 256>>>(E, ubp, out);                    // -> hc
}

// round 3
// speedup vs baseline: 1.8693x; 1.8693x over previous
#include <cuda_runtime.h>
#include <cuda_bf16.h>
#include <math.h>
#include <stdint.h>

#define NN    2048
#define BATCH 16
#define DEMB  10
#define CTOT  128            // C_IN + C_OUT
#define CO    64
#define BC    (BATCH*CTOT)   // 2048
#define BZ    (BATCH*CO)     // 1024
#define KC    (3*CTOT)       // 384
#define JG    (KC*CTOT)      // 49152
#define JU    (KC*CO)        // 24576

// ---------------- device scratch ----------------
__device__ float g_IAS[(size_t)NN*BC];
__device__ float g_XG1[(size_t)NN*BC];
__device__ float g_XG2[(size_t)NN*BC];
__device__ float g_Z  [(size_t)NN*BZ];
__device__ float g_ZG1[(size_t)NN*BZ];
__device__ float g_ZG2[(size_t)NN*BZ];
__device__ float g_Wg [(size_t)NN*JG];
__device__ float g_Wu [(size_t)NN*JU];
// bf16 split operands
__device__ __nv_bfloat16 g_Shi[(size_t)NN*NN];
__device__ __nv_bfloat16 g_Slo[(size_t)NN*NN];
__device__ __nv_bfloat16 g_ThT[(size_t)NN*NN];   // transposed B operand (hi), reused
__device__ __nv_bfloat16 g_TlT[(size_t)NN*NN];   // transposed B operand (lo), reused

// ---------------- pickers ----------------
__device__ __forceinline__ const float* pickIn(int id){
  switch(id){ case 0: return g_IAS; case 1: return g_XG1; case 2: return g_XG2;
              case 3: return g_Z;   case 4: return g_ZG1; }
  return g_IAS;
}
__device__ __forceinline__ float* pickOut(int id){
  switch(id){ case 1: return g_XG1; case 2: return g_XG2;
              case 4: return g_ZG1; case 5: return g_ZG2; }
  return g_XG1;
}

// ---------------- warp reductions ----------------
__device__ __forceinline__ float warpMax(float v){
  #pragma unroll
  for(int o=16;o;o>>=1) v = fmaxf(v, __shfl_xor_sync(0xffffffffu, v, o));
  return v;
}
__device__ __forceinline__ float warpSum(float v){
  #pragma unroll
  for(int o=16;o;o>>=1) v += __shfl_xor_sync(0xffffffffu, v, o);
  return v;
}

// ---------------- PTX helpers (compute_103-safe: no arch-suffix features) ----
__device__ __forceinline__ uint32_t smem_u32(const void* p){
  uint32_t a;
  asm("{ .reg .u64 t; cvta.to.shared.u64 t, %1; cvt.u32.u64 %0, t; }" : "=r"(a) : "l"(p));
  return a;
}
__device__ __forceinline__ void cp16(uint32_t s, const void* g){
  asm volatile("cp.async.cg.shared.global [%0], [%1], 16;" :: "r"(s), "l"(g) : "memory");
}
__device__ __forceinline__ void cp_commit(){ asm volatile("cp.async.commit_group;" ::: "memory"); }
__device__ __forceinline__ void ldsm_x4(uint32_t* r, uint32_t a){
  asm volatile("ldmatrix.sync.aligned.m8n8.x4.shared.b16 {%0,%1,%2,%3}, [%4];"
    : "=r"(r[0]),"=r"(r[1]),"=r"(r[2]),"=r"(r[3]) : "r"(a));
}
__device__ __forceinline__ void ldsm_x2(uint32_t* r, uint32_t a){
  asm volatile("ldmatrix.sync.aligned.m8n8.x2.shared.b16 {%0,%1}, [%2];"
    : "=r"(r[0]),"=r"(r[1]) : "r"(a));
}
__device__ __forceinline__ void mma16816(float* d, const uint32_t* a, const uint32_t* b){
  asm volatile("mma.sync.aligned.m16n8k16.row.col.f32.bf16.bf16.f32 "
    "{%0,%1,%2,%3}, {%4,%5,%6,%7}, {%8,%9}, {%0,%1,%2,%3};"
    : "+f"(d[0]),"+f"(d[1]),"+f"(d[2]),"+f"(d[3])
    : "r"(a[0]),"r"(a[1]),"r"(a[2]),"r"(a[3]), "r"(b[0]),"r"(b[1]));
}

// ---------------- K1: S row softmax -> bf16 hi/lo ----------------
__global__ void __launch_bounds__(256) k_supports(const float* __restrict__ E){
  __shared__ float sh[8];
  __shared__ float bcast;
  int row = blockIdx.x, tid = threadIdx.x;
  float Er[DEMB];
  #pragma unroll
  for(int d=0; d<DEMB; d++) Er[d] = E[row*DEMB + d];
  float a[8], m = -1e30f;
  #pragma unroll
  for(int q=0; q<8; q++){
    int col = tid + q*256;
    const float* Ec = E + (size_t)col*DEMB;
    float s = 0.f;
    #pragma unroll
    for(int d=0; d<DEMB; d++) s += Er[d]*Ec[d];
    s = fmaxf(s, 0.f);
    a[q] = s; m = fmaxf(m, s);
  }
  m = warpMax(m);
  if((tid&31)==0) sh[tid>>5] = m;
  __syncthreads();
  if(tid<32){ float t = (tid<8)? sh[tid] : -1e30f; t = warpMax(t); if(tid==0) bcast = t; }
  __syncthreads();
  m = bcast;
  float ssum = 0.f;
  #pragma unroll
  for(int q=0; q<8; q++){ a[q] = expf(a[q]-m); ssum += a[q]; }
  ssum = warpSum(ssum);
  __syncthreads();
  if((tid&31)==0) sh[tid>>5] = ssum;
  __syncthreads();
  if(tid<32){ float t = (tid<8)? sh[tid] : 0.f; t = warpSum(t); if(tid==0) bcast = t; }
  __syncthreads();
  float inv = 1.f/bcast;
  #pragma unroll
  for(int q=0; q<8; q++){
    float v = a[q]*inv;
    __nv_bfloat16 hi = __float2bfloat16(v);
    __nv_bfloat16 lo = __float2bfloat16(v - __bfloat162float(hi));
    size_t o = (size_t)row*NN + tid + q*256;
    g_Shi[o] = hi; g_Slo[o] = lo;
  }
}

// ---------------- K2: pack IAS ----------------
__global__ void __launch_bounds__(256) k_pack(const float* __restrict__ x,
                                              const float* __restrict__ st){
  int t = blockIdx.x*256 + threadIdx.x;
  int e = t*4;
  int n = e >> 11;
  int r = e & 2047;
  int b = r >> 7;
  int c = r & 127;
  float4 v;
  if (c < 64) v = *(const float4*)(x  + ((size_t)b*NN + n)*64 + c);
  else        v = *(const float4*)(st + ((size_t)b*NN + n)*64 + (c-64));
  *(float4*)(g_IAS + e) = v;
}

// -------- convert+transpose fp32 [2048 x W] -> bf16 hi/lo [W x 2048] --------
__global__ void __launch_bounds__(256) k_cvtT(int srcId, int W){
  const float* src = pickIn(srcId);
  __shared__ float t[32][33];
  int tx = threadIdx.x & 31, ty = threadIdx.x >> 5;
  int c0 = blockIdx.x*32, r0 = blockIdx.y*32;
  #pragma unroll
  for(int j=0;j<4;j++)
    t[ty+8*j][tx] = src[(size_t)(r0+ty+8*j)*W + c0+tx];
  __syncthreads();
  #pragma unroll
  for(int j=0;j<4;j++){
    float v = t[tx][ty+8*j];
    __nv_bfloat16 hi = __float2bfloat16(v);
    __nv_bfloat16 lo = __float2bfloat16(v - __bfloat162float(hi));
    size_t o = (size_t)(c0+ty+8*j)*NN + r0 + tx;
    g_ThT[o] = hi; g_TlT[o] = lo;
  }
}

// ---------------- K5: W[n,j] = sum_d E[n,d]*wp[d,j] ----------------
__global__ void __launch_bounds__(256) k_wcombine(const float* __restrict__ E,
                                                  const float* __restrict__ wp,
                                                  int J, int which){
  float* out = which ? g_Wu : g_Wg;
  int j  = blockIdx.x*256 + threadIdx.x;
  int n0 = blockIdx.y*32;
  float w[DEMB];
  #pragma unroll
  for(int d=0; d<DEMB; d++) w[d] = wp[(size_t)d*J + j];
  __shared__ float Es[32*DEMB];
  for(int t=threadIdx.x; t<32*DEMB; t+=256) Es[t] = E[n0*DEMB + t];
  __syncthreads();
  #pragma unroll 4
  for(int nn=0; nn<32; nn++){
    float acc = 0.f;
    #pragma unroll
    for(int d=0; d<DEMB; d++) acc += Es[nn*DEMB+d]*w[d];
    out[(size_t)(n0+nn)*J + j] = acc;
  }
}

// ---------------- HMMA bf16x3 GEMM: C = S@B (MODE0) or 2*S@B - D (MODE1) ----
// A = S hi/lo [2048 x 2048] (row-major, K-major).
// B = g_ThT/g_TlT [Ncols x 2048] (row-major, K-major).
// CTA tile 128x128, K-chunk 32, double-buffered cp.async.
// smem tile: 128 rows x 32 bf16, row stride 40 elems (80B) -> conflict-free ldmatrix.
#define TILE_B   10240                  // 128*40*2 bytes
#define BUF_B    (4*TILE_B)             // Ahi, Alo, Bhi, Blo
#define SM_TOT   (2*BUF_B)              // 81920

template<int MODE>
__global__ void __launch_bounds__(256) mma_gemm(int cId, int dId, int Ncols){
  extern __shared__ char smem[];
  float*       C = pickOut(cId);
  const float* D = pickIn(dId);
  const uint32_t sb = smem_u32(smem);
  const int tid = threadIdx.x, wid = tid >> 5, lane = tid & 31;
  const int warpM = wid & 3, warpN = wid >> 2;
  const size_t row0 = (size_t)blockIdx.y * 128;
  const size_t n0   = (size_t)blockIdx.x * 128;

  // cp.async source/dest indexing: u = tid + j*256 -> row = u>>2, quad = u&3
  const int ldr = tid >> 2, ldq = tid & 3;

  float acc[2][8][4];
  #pragma unroll
  for(int m=0;m<2;m++)
    #pragma unroll
    for(int n=0;n<8;n++)
      #pragma unroll
      for(int q=0;q<4;q++) acc[m][n][q] = 0.f;

  auto issue = [&](int c){
    const size_t kb = (size_t)c * 32;
    const uint32_t bo = sb + (uint32_t)(c & 1) * BUF_B;
    #pragma unroll
    for(int j=0;j<2;j++){
      int r = ldr + j*64, q = ldq;
      uint32_t so = (uint32_t)(r*80 + q*16);
      size_t gA = (row0 + r)*(size_t)NN + kb + q*8;
      size_t gB = (n0   + r)*(size_t)NN + kb + q*8;
      cp16(bo + 0*TILE_B + so, g_Shi + gA);
      cp16(bo + 1*TILE_B + so, g_Slo + gA);
      cp16(bo + 2*TILE_B + so, g_ThT + gB);
      cp16(bo + 3*TILE_B + so, g_TlT + gB);
    }
    cp_commit();
  };

  issue(0);
  for(int c=0; c<64; c++){
    if(c+1 < 64){
      issue(c+1);
      asm volatile("cp.async.wait_group 1;" ::: "memory");
    } else {
      asm volatile("cp.async.wait_group 0;" ::: "memory");
    }
    __syncthreads();

    const uint32_t bo = sb + (uint32_t)(c & 1) * BUF_B;
    #pragma unroll
    for(int ks=0; ks<2; ks++){
      uint32_t af[2][2][4];     // [split][mtile]
      #pragma unroll
      for(int mt=0; mt<2; mt++){
        uint32_t ad = bo + (uint32_t)((warpM*32 + mt*16 + (lane & 15))*80
                                      + ks*32 + (lane >> 4)*16);
        ldsm_x4(af[0][mt], ad);
        ldsm_x4(af[1][mt], ad + TILE_B);
      }
      uint32_t bf[2][8][2];     // [split][ntile]
      #pragma unroll
      for(int nt=0; nt<8; nt++){
        uint32_t bd = bo + 2*TILE_B
                    + (uint32_t)((warpN*64 + nt*8 + (lane & 7))*80
                                 + ks*32 + ((lane >> 3) & 1)*16);
        ldsm_x2(bf[0][nt], bd);
        ldsm_x2(bf[1][nt], bd + TILE_B);
      }
      #pragma unroll
      for(int mt=0; mt<2; mt++)
        #pragma unroll
        for(int nt=0; nt<8; nt++){
          mma16816(acc[mt][nt], af[0][mt], bf[0][nt]);   // Ah*Bh
          mma16816(acc[mt][nt], af[0][mt], bf[1][nt]);   // Ah*Bl
          mma16816(acc[mt][nt], af[1][mt], bf[0][nt]);   // Al*Bh
        }
    }
    __syncthreads();
  }

  // ---------------- epilogue ----------------
  const int g = lane >> 2, tg = lane & 3;
  #pragma unroll
  for(int mt=0; mt<2; mt++){
    size_t r0g = row0 + warpM*32 + mt*16 + g;
    #pragma unroll
    for(int nt=0; nt<8; nt++){
      size_t col = n0 + warpN*64 + nt*8 + tg*2;
      size_t o0 = r0g      *(size_t)Ncols + col;
      size_t o1 = (r0g + 8)*(size_t)Ncols + col;
      float2 v0 = make_float2(acc[mt][nt][0], acc[mt][nt][1]);
      float2 v1 = make_float2(acc[mt][nt][2], acc[mt][nt][3]);
      if(MODE == 1){
        float2 d0 = *(const float2*)(D + o0);
        float2 d1 = *(const float2*)(D + o1);
        v0.x = 2.f*v0.x - d0.x; v0.y = 2.f*v0.y - d0.y;
        v1.x = 2.f*v1.x - d1.x; v1.y = 2.f*v1.y - d1.y;
      }
      *(float2*)(C + o0) = v0;
      *(float2*)(C + o1) = v1;
    }
  }
}

// ---------------- K6: gate final ----------------
__global__ void __launch_bounds__(256) k_gate_final(const float* __restrict__ E,
                                                    const float* __restrict__ gbp,
                                                    const float* __restrict__ lw,
                                                    const float* __restrict__ lb){
  __shared__ float smA[128*65];
  __shared__ float ysig[BATCH*CTOT];
  __shared__ float Es[DEMB];
  int n = blockIdx.x, tid = threadIdx.x;

  float* Xs = smA;
  for(int t=tid; t<512; t+=256){
    ((float4*)Xs)[t]        = ((const float4*)(g_IAS + (size_t)n*BC))[t];
    ((float4*)(Xs+2048))[t] = ((const float4*)(g_XG1 + (size_t)n*BC))[t];
    ((float4*)(Xs+4096))[t] = ((const float4*)(g_XG2 + (size_t)n*BC))[t];
  }
  if(tid<DEMB) Es[tid] = E[n*DEMB + tid];
  __syncthreads();

  int o  = tid & 127;
  int bg = tid >> 7;
  float bias = 0.f;
  #pragma unroll
  for(int d=0; d<DEMB; d++) bias += Es[d]*gbp[d*CTOT + o];
  float acc[8];
  #pragma unroll
  for(int bb=0; bb<8; bb++) acc[bb] = bias;

  const float* W = g_Wg + (size_t)n*JG + o;
  #pragma unroll 4
  for(int j=0; j<KC; j++){
    float w = W[(size_t)j*CTOT];
    int k = j >> 7, i = j & 127;
    const float* Xk = Xs + k*2048 + i;
    #pragma unroll
    for(int bb=0; bb<8; bb++) acc[bb] += w * Xk[(bg*8+bb)*CTOT];
  }
  #pragma unroll
  for(int bb=0; bb<8; bb++){
    float v = 1.f/(1.f + expf(-acc[bb]));
    ysig[(bg*8+bb)*CTOT + o] = v;
  }
  __syncthreads();

  float* lwT = smA;
  for(int t=tid; t<CO*CTOT; t+=256){ int c = t>>7, oo = t&127; lwT[oo*65 + c] = lw[t]; }
  __syncthreads();

  int c   = tid & 63;
  int bg2 = tid >> 6;
  float acc2[4];
  float lbv = lb[c];
  #pragma unroll
  for(int bb=0; bb<4; bb++) acc2[bb] = lbv;
  #pragma unroll 4
  for(int o2=0; o2<CTOT; o2++){
    float w = lwT[o2*65 + c];
    #pragma unroll
    for(int bb=0; bb<4; bb++) acc2[bb] += ysig[(bg2*4+bb)*CTOT + o2]*w;
  }
  #pragma unroll
  for(int bb=0; bb<4; bb++)
    g_Z[(size_t)n*BZ + (bg2*4+bb)*CO + c] = acc2[bb];
}

// ---------------- K9: upd final ----------------
__global__ void __launch_bounds__(256) k_upd_final(const float* __restrict__ E,
                                                   const float* __restrict__ ubp,
                                                   float* __restrict__ out){
  __shared__ float Xs[3*2048];
  __shared__ float Zs[3*1024];
  __shared__ float Es[DEMB];
  int n = blockIdx.x, tid = threadIdx.x;
  for(int t=tid; t<512; t+=256){
    ((float4*)Xs)[t]        = ((const float4*)(g_IAS + (size_t)n*BC))[t];
    ((float4*)(Xs+2048))[t] = ((const float4*)(g_XG1 + (size_t)n*BC))[t];
    ((float4*)(Xs+4096))[t] = ((const float4*)(g_XG2 + (size_t)n*BC))[t];
  }
  if (tid < 256){
    ((float4*)Zs)[tid]        = ((const float4*)(g_Z   + (size_t)n*BZ))[tid];
    ((float4*)(Zs+1024))[tid] = ((const float4*)(g_ZG1 + (size_t)n*BZ))[tid];
    ((float4*)(Zs+2048))[tid] = ((const float4*)(g_ZG2 + (size_t)n*BZ))[tid];
  }
  if(tid<DEMB) Es[tid] = E[n*DEMB + tid];
  __syncthreads();

  int o  = tid & 63;
  int bg = tid >> 6;
  float bias = 0.f;
  #pragma unroll
  for(int d=0; d<DEMB; d++) bias += Es[d]*ubp[d*CO + o];
  float acc[4];
  #pragma unroll
  for(int bb=0; bb<4; bb++) acc[bb] = bias;

  const float* W = g_Wu + (size_t)n*JU + o;
  #pragma unroll
  for(int k=0; k<3; k++){
    #pragma unroll 4
    for(int i=0; i<64; i++){
      float w = W[(size_t)(k*128 + i)*CO];
      #pragma unroll
      for(int bb=0; bb<4; bb++) acc[bb] += w * Xs[k*2048 + (bg*4+bb)*CTOT + i];
    }
    #pragma unroll 4
    for(int i=0; i<64; i++){
      float w = W[(size_t)(k*128 + 64 + i)*CO];
      #pragma unroll
      for(int bb=0; bb<4; bb++) acc[bb] += w * Zs[k*1024 + (bg*4+bb)*CO + i];
    }
  }
  #pragma unroll
  for(int bb=0; bb<4; bb++)
    out[(size_t)(bg*4+bb)*((size_t)NN*CO) + (size_t)n*CO + o] = tanhf(acc[bb]);
}

// ---------------- launch ----------------
extern "C" void kernel_launch(void* const* d_in, const int* in_sizes, int n_in,
                              void* d_out, int out_size){
  (void)in_sizes; (void)n_in; (void)out_size;
  const float* x   = (const float*)d_in[0];
  const float* st  = (const float*)d_in[1];
  const float* E   = (const float*)d_in[2];
  const float* gwp = (const float*)d_in[3];
  const float* gbp = (const float*)d_in[4];
  const float* uwp = (const float*)d_in[5];
  const float* ubp = (const float*)d_in[6];
  const float* lw  = (const float*)d_in[7];
  const float* lb  = (const float*)d_in[8];
  float* out = (float*)d_out;

  static int attr_set = 0;
  if(!attr_set){
    cudaFuncSetAttribute(mma_gemm<0>, cudaFuncAttributeMaxDynamicSharedMemorySize, SM_TOT);
    cudaFuncSetAttribute(mma_gemm<1>, cudaFuncAttributeMaxDynamicSharedMemorySize, SM_TOT);
    attr_set = 1;
  }

  k_supports<<<NN, 256>>>(E);
  k_pack<<<(NN*BC/4)/256, 256>>>(x, st);
  k_wcombine<<<dim3(JG/256, NN/32), 256>>>(E, gwp, JG, 0);
  k_wcombine<<<dim3(JU/256, NN/32), 256>>>(E, uwp, JU, 1);

  k_cvtT<<<dim3(BC/32, NN/32), 256>>>(0, BC);                       // IAS -> T
  mma_gemm<0><<<dim3(BC/128, NN/128), 256, SM_TOT>>>(1, 0, BC);     // XG1 = S@IAS
  k_cvtT<<<dim3(BC/32, NN/32), 256>>>(1, BC);                       // XG1 -> T
  mma_gemm<1><<<dim3(BC/128, NN/128), 256, SM_TOT>>>(2, 0, BC);     // XG2 = 2*S@XG1 - IAS

  k_gate_final<<<NN, 256>>>(E, gbp, lw, lb);                        // -> g_Z

  k_cvtT<<<dim3(BZ/32, NN/32), 256>>>(3, BZ);                       // Z -> T
  mma_gemm<0><<<dim3(BZ/128, NN/128), 256, SM_TOT>>>(4, 3, BZ);     // ZG1 = S@Z
  k_cvtT<<<dim3(BZ/32, NN/32), 256>>>(4, BZ);                       // ZG1 -> T
  mma_gemm<1><<<dim3(BZ/128, NN/128), 256, SM_TOT>>>(5, 3, BZ);     // ZG2 = 2*S@ZG1 - Z

  k_upd_final<<<NN, 256>>>(E, ubp, out);                            // -> hc
}

// round 4
// speedup vs baseline: 1.8915x; 1.0119x over previous
#include <cuda_runtime.h>
#include <cuda_bf16.h>
#include <math.h>
#include <stdint.h>

#define NN    2048
#define BATCH 16
#define DEMB  10
#define CTOT  128            // C_IN + C_OUT
#define CO    64
#define BC    (BATCH*CTOT)   // 2048
#define BZ    (BATCH*CO)     // 1024
#define KC    (3*CTOT)       // 384
#define JG    (KC*CTOT)      // 49152
#define JU    (KC*CO)        // 24576

// ---------------- device scratch ----------------
__device__ float g_IAS[(size_t)NN*BC];
__device__ float g_XG1[(size_t)NN*BC];
__device__ float g_XG2[(size_t)NN*BC];
__device__ float g_Z  [(size_t)NN*BZ];
__device__ float g_ZG1[(size_t)NN*BZ];
__device__ float g_ZG2[(size_t)NN*BZ];
__device__ float g_Wg [(size_t)NN*JG];
__device__ float g_Wu [(size_t)NN*JU];
// bf16 split operands (16B aligned for cp.async)
__device__ __align__(256) __nv_bfloat16 g_Shi[(size_t)NN*NN];
__device__ __align__(256) __nv_bfloat16 g_Slo[(size_t)NN*NN];
__device__ __align__(256) __nv_bfloat16 g_TaH[(size_t)NN*NN];
__device__ __align__(256) __nv_bfloat16 g_TaL[(size_t)NN*NN];
__device__ __align__(256) __nv_bfloat16 g_TbH[(size_t)NN*NN];
__device__ __align__(256) __nv_bfloat16 g_TbL[(size_t)NN*NN];

// ---------------- pickers ----------------
__device__ __forceinline__ const float* pickIn(int id){
  switch(id){ case 0: return g_IAS; case 1: return g_XG1; case 2: return g_XG2;
              case 3: return g_Z;   case 4: return g_ZG1; }
  return g_IAS;
}
__device__ __forceinline__ float* pickOut(int id){
  switch(id){ case 1: return g_XG1; case 2: return g_XG2;
              case 4: return g_ZG1; case 5: return g_ZG2; }
  return g_XG1;
}
__device__ __forceinline__ __nv_bfloat16* pickBF(int id){
  switch(id){ case 0: return g_TaH; case 1: return g_TaL;
              case 2: return g_TbH; case 3: return g_TbL; }
  return g_TaH;
}

// ---------------- warp reductions ----------------
__device__ __forceinline__ float warpMax(float v){
  #pragma unroll
  for(int o=16;o;o>>=1) v = fmaxf(v, __shfl_xor_sync(0xffffffffu, v, o));
  return v;
}
__device__ __forceinline__ float warpSum(float v){
  #pragma unroll
  for(int o=16;o;o>>=1) v += __shfl_xor_sync(0xffffffffu, v, o);
  return v;
}

// ---------------- PTX helpers ----------------
__device__ __forceinline__ uint32_t smem_u32(const void* p){
  uint32_t a;
  asm("{ .reg .u64 t; cvta.to.shared.u64 t, %1; cvt.u32.u64 %0, t; }" : "=r"(a) : "l"(p));
  return a;
}
__device__ __forceinline__ void cp16(uint32_t s, const void* g){
  asm volatile("cp.async.cg.shared.global [%0], [%1], 16;" :: "r"(s), "l"(g) : "memory");
}
__device__ __forceinline__ void cp_commit(){ asm volatile("cp.async.commit_group;" ::: "memory"); }
__device__ __forceinline__ void ldsm_x4(uint32_t* r, uint32_t a){
  asm volatile("ldmatrix.sync.aligned.m8n8.x4.shared.b16 {%0,%1,%2,%3}, [%4];"
    : "=r"(r[0]),"=r"(r[1]),"=r"(r[2]),"=r"(r[3]) : "r"(a));
}
__device__ __forceinline__ void mma16816(float* d, const uint32_t* a, const uint32_t* b){
  asm volatile("mma.sync.aligned.m16n8k16.row.col.f32.bf16.bf16.f32 "
    "{%0,%1,%2,%3}, {%4,%5,%6,%7}, {%8,%9}, {%0,%1,%2,%3};"
    : "+f"(d[0]),"+f"(d[1]),"+f"(d[2]),"+f"(d[3])
    : "r"(a[0]),"r"(a[1]),"r"(a[2]),"r"(a[3]), "r"(b[0]),"r"(b[1]));
}

// ---------------- K1: S row softmax -> bf16 hi/lo ----------------
__global__ void __launch_bounds__(256) k_supports(const float* __restrict__ E){
  __shared__ float sh[8];
  __shared__ float bcast;
  int row = blockIdx.x, tid = threadIdx.x;
  float Er[DEMB];
  #pragma unroll
  for(int d=0; d<DEMB; d++) Er[d] = E[row*DEMB + d];
  float a[8], m = -1e30f;
  #pragma unroll
  for(int q=0; q<8; q++){
    int col = tid + q*256;
    const float* Ec = E + (size_t)col*DEMB;
    float s = 0.f;
    #pragma unroll
    for(int d=0; d<DEMB; d++) s += Er[d]*Ec[d];
    s = fmaxf(s, 0.f);
    a[q] = s; m = fmaxf(m, s);
  }
  m = warpMax(m);
  if((tid&31)==0) sh[tid>>5] = m;
  __syncthreads();
  if(tid<32){ float t = (tid<8)? sh[tid] : -1e30f; t = warpMax(t); if(tid==0) bcast = t; }
  __syncthreads();
  m = bcast;
  float ssum = 0.f;
  #pragma unroll
  for(int q=0; q<8; q++){ a[q] = expf(a[q]-m); ssum += a[q]; }
  ssum = warpSum(ssum);
  __syncthreads();
  if((tid&31)==0) sh[tid>>5] = ssum;
  __syncthreads();
  if(tid<32){ float t = (tid<8)? sh[tid] : 0.f; t = warpSum(t); if(tid==0) bcast = t; }
  __syncthreads();
  float inv = 1.f/bcast;
  #pragma unroll
  for(int q=0; q<8; q++){
    float v = a[q]*inv;
    __nv_bfloat16 hi = __float2bfloat16(v);
    __nv_bfloat16 lo = __float2bfloat16(v - __bfloat162float(hi));
    size_t o = (size_t)row*NN + tid + q*256;
    g_Shi[o] = hi; g_Slo[o] = lo;
  }
}

// ---------------- K2: pack IAS ----------------
__global__ void __launch_bounds__(256) k_pack(const float* __restrict__ x,
                                              const float* __restrict__ st){
  int t = blockIdx.x*256 + threadIdx.x;
  int e = t*4;
  int n = e >> 11;
  int r = e & 2047;
  int b = r >> 7;
  int c = r & 127;
  float4 v;
  if (c < 64) v = *(const float4*)(x  + ((size_t)b*NN + n)*64 + c);
  else        v = *(const float4*)(st + ((size_t)b*NN + n)*64 + (c-64));
  *(float4*)(g_IAS + e) = v;
}

// -------- convert+transpose fp32 [2048 x W] -> bf16 hi/lo [W x 2048] --------
__global__ void __launch_bounds__(256) k_cvtT(int srcId, int W, int dstHi){
  const float* src = pickIn(srcId);
  __nv_bfloat16* dH = pickBF(dstHi);
  __nv_bfloat16* dL = pickBF(dstHi+1);
  __shared__ float t[32][33];
  int tx = threadIdx.x & 31, ty = threadIdx.x >> 5;
  int c0 = blockIdx.x*32, r0 = blockIdx.y*32;
  #pragma unroll
  for(int j=0;j<4;j++)
    t[ty+8*j][tx] = src[(size_t)(r0+ty+8*j)*W + c0+tx];
  __syncthreads();
  #pragma unroll
  for(int j=0;j<4;j++){
    float v = t[tx][ty+8*j];
    __nv_bfloat16 hi = __float2bfloat16(v);
    __nv_bfloat16 lo = __float2bfloat16(v - __bfloat162float(hi));
    size_t o = (size_t)(c0+ty+8*j)*NN + r0 + tx;
    dH[o] = hi; dL[o] = lo;
  }
}

// ---------------- K5: W[n,j4] = sum_d E[n,d]*wp[d,j4] (float4) ----------------
__global__ void __launch_bounds__(256) k_wcombine(const float* __restrict__ E,
                                                  const float* __restrict__ wp,
                                                  int J, int which){
  float* out = which ? g_Wu : g_Wg;
  int j  = (blockIdx.x*256 + threadIdx.x)*4;
  int n0 = blockIdx.y*32;
  float4 w[DEMB];
  #pragma unroll
  for(int d=0; d<DEMB; d++) w[d] = *(const float4*)(wp + (size_t)d*J + j);
  __shared__ float Es[32*DEMB];
  for(int t=threadIdx.x; t<32*DEMB; t+=256) Es[t] = E[n0*DEMB + t];
  __syncthreads();
  #pragma unroll 2
  for(int nn=0; nn<32; nn++){
    float4 a = make_float4(0.f,0.f,0.f,0.f);
    #pragma unroll
    for(int d=0; d<DEMB; d++){
      float e = Es[nn*DEMB+d];
      a.x += e*w[d].x; a.y += e*w[d].y; a.z += e*w[d].z; a.w += e*w[d].w;
    }
    *(float4*)(out + (size_t)(n0+nn)*J + j) = a;
  }
}

// ---------------- HMMA bf16x3 GEMM, 4-stage cp.async pipeline ----------------
// A = S hi/lo [2048 x 2048], B = T hi/lo [Ncols x 2048] (both K-major).
// CTA tile 128x128, K-chunk 16, 4 stages. Row pitch 48B (conflict-free ldmatrix).
#define PITCH    48                      // bytes per 16-col bf16 row
#define TILE_B   (128*PITCH)             // 6144
#define STAGE_B  (4*TILE_B)              // 24576: Ahi, Alo, Bhi, Blo
#define NSTAGE   4
#define SM_TOT   (NSTAGE*STAGE_B)        // 98304

template<int MODE, int WRITE_T>
__global__ void __launch_bounds__(256,2) mma_gemm(int cId, int dId, int Ncols,
                                                  int bHiId, int tHiId){
  extern __shared__ char smem[];
  float*       C = pickOut(cId);
  const float* D = pickIn(dId);
  const __nv_bfloat16* Bh = pickBF(bHiId);
  const __nv_bfloat16* Bl = pickBF(bHiId+1);
  const uint32_t sb = smem_u32(smem);
  const int tid = threadIdx.x, wid = tid >> 5, lane = tid & 31;
  const int warpM = wid & 3, warpN = wid >> 2;
  const size_t row0 = (size_t)blockIdx.y * 128;
  const size_t n0   = (size_t)blockIdx.x * 128;

  const int ldrow = tid >> 1, ldh = tid & 1;     // cp.async mapping

  float acc[2][8][4];
  #pragma unroll
  for(int m=0;m<2;m++)
    #pragma unroll
    for(int n=0;n<8;n++)
      #pragma unroll
      for(int q=0;q<4;q++) acc[m][n][q] = 0.f;

  auto issue = [&](int c){
    const size_t kb = (size_t)c * 16;
    const uint32_t bo = sb + (uint32_t)(c & 3) * STAGE_B;
    const uint32_t so = (uint32_t)(ldrow*PITCH + ldh*16);
    size_t gA = (row0 + ldrow)*(size_t)NN + kb + ldh*8;
    size_t gB = (n0   + ldrow)*(size_t)NN + kb + ldh*8;
    cp16(bo + 0*TILE_B + so, g_Shi + gA);
    cp16(bo + 1*TILE_B + so, g_Slo + gA);
    cp16(bo + 2*TILE_B + so, Bh + gB);
    cp16(bo + 3*TILE_B + so, Bl + gB);
    cp_commit();
  };

  issue(0); issue(1); issue(2);

  const uint32_t aoff = (uint32_t)((warpM*32 + (lane & 15))*PITCH + (lane >> 4)*16);
  const uint32_t boff = (uint32_t)((warpN*64 + ((lane >> 4) & 1)*8 + (lane & 7))*PITCH
                                   + ((lane >> 3) & 1)*16);

  for(int c=0; c<128; c++){
    if(c <= 125)      asm volatile("cp.async.wait_group 2;" ::: "memory");
    else if(c == 126) asm volatile("cp.async.wait_group 1;" ::: "memory");
    else              asm volatile("cp.async.wait_group 0;" ::: "memory");
    __syncthreads();
    if(c + 3 < 128) issue(c+3);

    const uint32_t bo = sb + (uint32_t)(c & 3) * STAGE_B;
    uint32_t afH[2][4], afL[2][4];
    #pragma unroll
    for(int mt=0; mt<2; mt++){
      uint32_t ad = bo + aoff + (uint32_t)(mt*16*PITCH);
      ldsm_x4(afH[mt], ad);
      ldsm_x4(afL[mt], ad + TILE_B);
    }
    #pragma unroll
    for(int ntp=0; ntp<4; ntp++){
      uint32_t bd = bo + 2*TILE_B + boff + (uint32_t)(ntp*16*PITCH);
      uint32_t bH[4], bL[4];
      ldsm_x4(bH, bd);
      ldsm_x4(bL, bd + TILE_B);
      #pragma unroll
      for(int mt=0; mt<2; mt++){
        mma16816(acc[mt][2*ntp],   afH[mt], bH);
        mma16816(acc[mt][2*ntp+1], afH[mt], bH+2);
        mma16816(acc[mt][2*ntp],   afH[mt], bL);
        mma16816(acc[mt][2*ntp+1], afH[mt], bL+2);
        mma16816(acc[mt][2*ntp],   afL[mt], bH);
        mma16816(acc[mt][2*ntp+1], afL[mt], bH+2);
      }
    }
  }

  // ---------------- epilogue: fp32 C (and optional transposed bf16 hi/lo) ----
  const int g = lane >> 2, tg = lane & 3;
  #pragma unroll
  for(int mt=0; mt<2; mt++){
    size_t r0g = row0 + warpM*32 + mt*16 + g;
    #pragma unroll
    for(int nt=0; nt<8; nt++){
      size_t col = n0 + warpN*64 + nt*8 + tg*2;
      size_t o0 = r0g      *(size_t)Ncols + col;
      size_t o1 = (r0g + 8)*(size_t)Ncols + col;
      float2 v0 = make_float2(acc[mt][nt][0], acc[mt][nt][1]);
      float2 v1 = make_float2(acc[mt][nt][2], acc[mt][nt][3]);
      if(MODE == 1){
        float2 d0 = *(const float2*)(D + o0);
        float2 d1 = *(const float2*)(D + o1);
        v0.x = 2.f*v0.x - d0.x; v0.y = 2.f*v0.y - d0.y;
        v1.x = 2.f*v1.x - d1.x; v1.y = 2.f*v1.y - d1.y;
      }
      *(float2*)(C + o0) = v0;
      *(float2*)(C + o1) = v1;
    }
  }

  if(WRITE_T){
    __nv_bfloat16* TH = pickBF(tHiId);
    __nv_bfloat16* TL = pickBF(tHiId+1);
    float* tile = (float*)smem;          // [128][132]
    __syncthreads();                     // pipeline smem dead
    #pragma unroll
    for(int mt=0; mt<2; mt++){
      int rr = warpM*32 + mt*16 + g;
      #pragma unroll
      for(int nt=0; nt<8; nt++){
        int cc = warpN*64 + nt*8 + tg*2;
        tile[rr*132 + cc]     = acc[mt][nt][0];
        tile[rr*132 + cc + 1] = acc[mt][nt][1];
        tile[(rr+8)*132 + cc]     = acc[mt][nt][2];
        tile[(rr+8)*132 + cc + 1] = acc[mt][nt][3];
      }
    }
    __syncthreads();
    int c0 = tid >> 1, half = tid & 1;
    size_t baseO = (size_t)(n0 + c0)*NN + row0 + half*64;
    #pragma unroll
    for(int ch=0; ch<8; ch++){
      __nv_bfloat16 hb[8], lb8[8];
      #pragma unroll
      for(int e=0; e<8; e++){
        float v = tile[(half*64 + ch*8 + e)*132 + c0];
        __nv_bfloat16 hi = __float2bfloat16(v);
        hb[e] = hi;
        lb8[e] = __float2bfloat16(v - __bfloat162float(hi));
      }
      *(uint4*)(TH + baseO + ch*8) = *(uint4*)hb;
      *(uint4*)(TL + baseO + ch*8) = *(uint4*)lb8;
    }
  }
}

// ---------------- K6: gate final ----------------
__global__ void __launch_bounds__(256) k_gate_final(const float* __restrict__ E,
                                                    const float* __restrict__ gbp,
                                                    const float* __restrict__ lw,
                                                    const float* __restrict__ lb){
  __shared__ float smA[128*68];        // phase1: Xs (6144 floats); phase2: lwT
  __shared__ float ysig[BATCH*CTOT];   // 2048
  __shared__ float bias[CTOT];
  int n = blockIdx.x, tid = threadIdx.x;

  float* Xs = smA;
  for(int t=tid; t<512; t+=256){
    ((float4*)Xs)[t]        = ((const float4*)(g_IAS + (size_t)n*BC))[t];
    ((float4*)(Xs+2048))[t] = ((const float4*)(g_XG1 + (size_t)n*BC))[t];
    ((float4*)(Xs+4096))[t] = ((const float4*)(g_XG2 + (size_t)n*BC))[t];
  }
  if(tid < CTOT){
    float b = 0.f;
    #pragma unroll
    for(int d=0; d<DEMB; d++) b += E[n*DEMB + d]*gbp[d*CTOT + tid];
    bias[tid] = b;
  }
  __syncthreads();

  int oq = (tid & 31)*4;
  int b0 = (tid >> 5)*2, b1 = b0 + 1;
  float acc[2][4];
  #pragma unroll
  for(int q=0;q<4;q++){ acc[0][q] = bias[oq+q]; acc[1][q] = bias[oq+q]; }

  const float* W = g_Wg + (size_t)n*JG + oq;
  #pragma unroll
  for(int k=0; k<3; k++){
    const float* Xk0 = Xs + k*2048 + b0*CTOT;
    const float* Xk1 = Xs + k*2048 + b1*CTOT;
    const float* Wk  = W + (size_t)k*128*CTOT;
    #pragma unroll 8
    for(int i=0; i<128; i++){
      float4 w4 = *(const float4*)(Wk + (size_t)i*CTOT);
      float x0 = Xk0[i], x1 = Xk1[i];
      acc[0][0] += x0*w4.x; acc[0][1] += x0*w4.y; acc[0][2] += x0*w4.z; acc[0][3] += x0*w4.w;
      acc[1][0] += x1*w4.x; acc[1][1] += x1*w4.y; acc[1][2] += x1*w4.z; acc[1][3] += x1*w4.w;
    }
  }
  #pragma unroll
  for(int bb=0; bb<2; bb++){
    float4 v;
    v.x = 1.f/(1.f + expf(-acc[bb][0]));
    v.y = 1.f/(1.f + expf(-acc[bb][1]));
    v.z = 1.f/(1.f + expf(-acc[bb][2]));
    v.w = 1.f/(1.f + expf(-acc[bb][3]));
    *(float4*)(ysig + (b0+bb)*CTOT + oq) = v;
  }
  __syncthreads();                     // Xs dead; ysig ready

  float* lwT = smA;                    // lwT[o*68 + c]
  for(int t=tid; t<CO*CTOT; t+=256){ int c = t>>7, oo = t&127; lwT[oo*68 + c] = lw[t]; }
  __syncthreads();

  int c4  = (tid & 15)*4;
  int bg  = tid >> 4;                  // 16 groups, 1 batch each
  float acc2[4];
  #pragma unroll
  for(int q=0;q<4;q++) acc2[q] = lb[c4+q];
  const float* Ys = ysig + bg*CTOT;
  #pragma unroll 8
  for(int o2=0; o2<CTOT; o2++){
    float4 w4 = *(const float4*)(lwT + o2*68 + c4);
    float y = Ys[o2];
    acc2[0] += y*w4.x; acc2[1] += y*w4.y; acc2[2] += y*w4.z; acc2[3] += y*w4.w;
  }
  *(float4*)(g_Z + (size_t)n*BZ + bg*CO + c4) = make_float4(acc2[0],acc2[1],acc2[2],acc2[3]);
}

// ---------------- K9: upd final ----------------
__global__ void __launch_bounds__(256) k_upd_final(const float* __restrict__ E,
                                                   const float* __restrict__ ubp,
                                                   float* __restrict__ out){
  __shared__ float Xs[3*1024];         // x-halves only
  __shared__ float Zs[3*1024];
  __shared__ float bias[CO];
  int n = blockIdx.x, tid = threadIdx.x;
  {
    const float* s0 = g_IAS + (size_t)n*BC;
    const float* s1 = g_XG1 + (size_t)n*BC;
    const float* s2 = g_XG2 + (size_t)n*BC;
    int b = tid >> 4, f = (tid & 15)*4;     // 256 threads = 16b x 16 quads
    ((float4*)(Xs       ))[tid] = *(const float4*)(s0 + b*CTOT + f);
    ((float4*)(Xs + 1024))[tid] = *(const float4*)(s1 + b*CTOT + f);
    ((float4*)(Xs + 2048))[tid] = *(const float4*)(s2 + b*CTOT + f);
    ((float4*)(Zs       ))[tid] = ((const float4*)(g_Z   + (size_t)n*BZ))[tid];
    ((float4*)(Zs + 1024))[tid] = ((const float4*)(g_ZG1 + (size_t)n*BZ))[tid];
    ((float4*)(Zs + 2048))[tid] = ((const float4*)(g_ZG2 + (size_t)n*BZ))[tid];
  }
  if(tid < CO){
    float b = 0.f;
    #pragma unroll
    for(int d=0; d<DEMB; d++) b += E[n*DEMB + d]*ubp[d*CO + tid];
    bias[tid] = b;
  }
  __syncthreads();

  int oq = (tid & 15)*4;
  int bg = tid >> 4;                   // 16 groups, 1 batch each
  float acc[4];
  #pragma unroll
  for(int q=0;q<4;q++) acc[q] = bias[oq+q];

  const float* W = g_Wu + (size_t)n*JU + oq;
  #pragma unroll
  for(int k=0; k<3; k++){
    const float* Xk = Xs + k*1024 + bg*CO;
    const float* Zk = Zs + k*1024 + bg*CO;
    const float* Wk = W + (size_t)k*128*CO;
    #pragma unroll 8
    for(int i=0; i<64; i++){
      float4 w4 = *(const float4*)(Wk + (size_t)i*CO);
      float x = Xk[i];
      acc[0] += x*w4.x; acc[1] += x*w4.y; acc[2] += x*w4.z; acc[3] += x*w4.w;
    }
    const float* Wk2 = Wk + (size_t)64*CO;
    #pragma unroll 8
    for(int i=0; i<64; i++){
      float4 w4 = *(const float4*)(Wk2 + (size_t)i*CO);
      float z = Zk[i];
      acc[0] += z*w4.x; acc[1] += z*w4.y; acc[2] += z*w4.z; acc[3] += z*w4.w;
    }
  }
  float4 v = make_float4(tanhf(acc[0]), tanhf(acc[1]), tanhf(acc[2]), tanhf(acc[3]));
  *(float4*)(out + ((size_t)bg*NN + n)*CO + oq) = v;
}

// ---------------- launch ----------------
extern "C" void kernel_launch(void* const* d_in, const int* in_sizes, int n_in,
                              void* d_out, int out_size){
  (void)in_sizes; (void)n_in; (void)out_size;
  const float* x   = (const float*)d_in[0];
  const float* st  = (const float*)d_in[1];
  const float* E   = (const float*)d_in[2];
  const float* gwp = (const float*)d_in[3];
  const float* gbp = (const float*)d_in[4];
  const float* uwp = (const float*)d_in[5];
  const float* ubp = (const float*)d_in[6];
  const float* lw  = (const float*)d_in[7];
  const float* lb  = (const float*)d_in[8];
  float* out = (float*)d_out;

  static int attr_set = 0;
  if(!attr_set){
    cudaFuncSetAttribute(mma_gemm<0,1>, cudaFuncAttributeMaxDynamicSharedMemorySize, SM_TOT);
    cudaFuncSetAttribute(mma_gemm<1,0>, cudaFuncAttributeMaxDynamicSharedMemorySize, SM_TOT);
    attr_set = 1;
  }

  k_supports<<<NN, 256>>>(E);
  k_pack<<<(NN*BC/4)/256, 256>>>(x, st);
  k_wcombine<<<dim3(JG/1024, NN/32), 256>>>(E, gwp, JG, 0);
  k_wcombine<<<dim3(JU/1024, NN/32), 256>>>(E, uwp, JU, 1);

  k_cvtT<<<dim3(BC/32, NN/32), 256>>>(0, BC, 0);                        // IAS -> Ta
  mma_gemm<0,1><<<dim3(BC/128, NN/128), 256, SM_TOT>>>(1, 0, BC, 0, 2); // XG1; T->Tb
  mma_gemm<1,0><<<dim3(BC/128, NN/128), 256, SM_TOT>>>(2, 0, BC, 2, 0); // XG2 = 2S@XG1-IAS

  k_gate_final<<<NN, 256>>>(E, gbp, lw, lb);                            // -> g_Z

  k_cvtT<<<dim3(BZ/32, NN/32), 256>>>(3, BZ, 0);                        // Z -> Ta
  mma_gemm<0,1><<<dim3(BZ/128, NN/128), 256, SM_TOT>>>(4, 3, BZ, 0, 2); // ZG1; T->Tb
  mma_gemm<1,0><<<dim3(BZ/128, NN/128), 256, SM_TOT>>>(5, 3, BZ, 2, 0); // ZG2 = 2S@ZG1-Z

  k_upd_final<<<NN, 256>>>(E, ubp, out);                                // -> hc
}

// round 5
// speedup vs baseline: 1.9477x; 1.0297x over previous
#include <cuda_runtime.h>
#include <cuda_bf16.h>
#include <math.h>
#include <stdint.h>

#define NN    2048
#define BATCH 16
#define DEMB  10
#define CTOT  128            // C_IN + C_OUT
#define CO    64
#define BC    (BATCH*CTOT)   // 2048
#define BZ    (BATCH*CO)     // 1024
#define KC    (3*CTOT)       // 384
#define JG    (KC*CTOT)      // 49152
#define JU    (KC*CO)        // 24576

// ---------------- device scratch ----------------
__device__ float g_IAS[(size_t)NN*BC];
__device__ float g_XG1[(size_t)NN*BC];
__device__ float g_XG2[(size_t)NN*BC];
__device__ float g_Z  [(size_t)NN*BZ];
__device__ float g_ZG1[(size_t)NN*BZ];
__device__ float g_ZG2[(size_t)NN*BZ];
__device__ float g_Wg [(size_t)NN*JG];
__device__ float g_Wu [(size_t)NN*JU];
// bf16 split operands (16B aligned for cp.async)
__device__ __align__(256) __nv_bfloat16 g_Shi[(size_t)NN*NN];
__device__ __align__(256) __nv_bfloat16 g_Slo[(size_t)NN*NN];
__device__ __align__(256) __nv_bfloat16 g_TaH[(size_t)NN*NN];
__device__ __align__(256) __nv_bfloat16 g_TaL[(size_t)NN*NN];
__device__ __align__(256) __nv_bfloat16 g_TbH[(size_t)NN*NN];
__device__ __align__(256) __nv_bfloat16 g_TbL[(size_t)NN*NN];

// ---------------- pickers ----------------
__device__ __forceinline__ const float* pickIn(int id){
  switch(id){ case 0: return g_IAS; case 1: return g_XG1; case 2: return g_XG2;
              case 3: return g_Z;   case 4: return g_ZG1; }
  return g_IAS;
}
__device__ __forceinline__ float* pickOut(int id){
  switch(id){ case 1: return g_XG1; case 2: return g_XG2;
              case 4: return g_ZG1; case 5: return g_ZG2; }
  return g_XG1;
}
__device__ __forceinline__ __nv_bfloat16* pickBF(int id){
  switch(id){ case 0: return g_TaH; case 1: return g_TaL;
              case 2: return g_TbH; case 3: return g_TbL; }
  return g_TaH;
}

// ---------------- warp reductions ----------------
__device__ __forceinline__ float warpMax(float v){
  #pragma unroll
  for(int o=16;o;o>>=1) v = fmaxf(v, __shfl_xor_sync(0xffffffffu, v, o));
  return v;
}
__device__ __forceinline__ float warpSum(float v){
  #pragma unroll
  for(int o=16;o;o>>=1) v += __shfl_xor_sync(0xffffffffu, v, o);
  return v;
}

// ---------------- PTX helpers ----------------
__device__ __forceinline__ uint32_t smem_u32(const void* p){
  uint32_t a;
  asm("{ .reg .u64 t; cvta.to.shared.u64 t, %1; cvt.u32.u64 %0, t; }" : "=r"(a) : "l"(p));
  return a;
}
__device__ __forceinline__ void cp16(uint32_t s, const void* g){
  asm volatile("cp.async.cg.shared.global [%0], [%1], 16;" :: "r"(s), "l"(g) : "memory");
}
__device__ __forceinline__ void cp_commit(){ asm volatile("cp.async.commit_group;" ::: "memory"); }
__device__ __forceinline__ void ldsm_x4(uint32_t* r, uint32_t a){
  asm volatile("ldmatrix.sync.aligned.m8n8.x4.shared.b16 {%0,%1,%2,%3}, [%4];"
    : "=r"(r[0]),"=r"(r[1]),"=r"(r[2]),"=r"(r[3]) : "r"(a));
}
__device__ __forceinline__ void mma16816(float* d, const uint32_t* a, const uint32_t* b){
  asm volatile("mma.sync.aligned.m16n8k16.row.col.f32.bf16.bf16.f32 "
    "{%0,%1,%2,%3}, {%4,%5,%6,%7}, {%8,%9}, {%0,%1,%2,%3};"
    : "+f"(d[0]),"+f"(d[1]),"+f"(d[2]),"+f"(d[3])
    : "r"(a[0]),"r"(a[1]),"r"(a[2]),"r"(a[3]), "r"(b[0]),"r"(b[1]));
}

// ---------------- K1: S row softmax -> bf16 hi/lo ----------------
__global__ void __launch_bounds__(256) k_supports(const float* __restrict__ E){
  __shared__ float sh[8];
  __shared__ float bcast;
  int row = blockIdx.x, tid = threadIdx.x;
  float Er[DEMB];
  #pragma unroll
  for(int d=0; d<DEMB; d++) Er[d] = E[row*DEMB + d];
  float a[8], m = -1e30f;
  #pragma unroll
  for(int q=0; q<8; q++){
    int col = tid + q*256;
    const float* Ec = E + (size_t)col*DEMB;
    float s = 0.f;
    #pragma unroll
    for(int d=0; d<DEMB; d++) s += Er[d]*Ec[d];
    s = fmaxf(s, 0.f);
    a[q] = s; m = fmaxf(m, s);
  }
  m = warpMax(m);
  if((tid&31)==0) sh[tid>>5] = m;
  __syncthreads();
  if(tid<32){ float t = (tid<8)? sh[tid] : -1e30f; t = warpMax(t); if(tid==0) bcast = t; }
  __syncthreads();
  m = bcast;
  float ssum = 0.f;
  #pragma unroll
  for(int q=0; q<8; q++){ a[q] = expf(a[q]-m); ssum += a[q]; }
  ssum = warpSum(ssum);
  __syncthreads();
  if((tid&31)==0) sh[tid>>5] = ssum;
  __syncthreads();
  if(tid<32){ float t = (tid<8)? sh[tid] : 0.f; t = warpSum(t); if(tid==0) bcast = t; }
  __syncthreads();
  float inv = 1.f/bcast;
  #pragma unroll
  for(int q=0; q<8; q++){
    float v = a[q]*inv;
    __nv_bfloat16 hi = __float2bfloat16(v);
    __nv_bfloat16 lo = __float2bfloat16(v - __bfloat162float(hi));
    size_t o = (size_t)row*NN + tid + q*256;
    g_Shi[o] = hi; g_Slo[o] = lo;
  }
}

// ---------------- K2: pack IAS ----------------
__global__ void __launch_bounds__(256) k_pack(const float* __restrict__ x,
                                              const float* __restrict__ st){
  int t = blockIdx.x*256 + threadIdx.x;
  int e = t*4;
  int n = e >> 11;
  int r = e & 2047;
  int b = r >> 7;
  int c = r & 127;
  float4 v;
  if (c < 64) v = *(const float4*)(x  + ((size_t)b*NN + n)*64 + c);
  else        v = *(const float4*)(st + ((size_t)b*NN + n)*64 + (c-64));
  *(float4*)(g_IAS + e) = v;
}

// -------- convert+transpose fp32 [2048 x W] -> bf16 hi/lo [W x 2048] --------
__global__ void __launch_bounds__(256) k_cvtT(int srcId, int W, int dstHi){
  const float* src = pickIn(srcId);
  __nv_bfloat16* dH = pickBF(dstHi);
  __nv_bfloat16* dL = pickBF(dstHi+1);
  __shared__ float t[32][33];
  int tx = threadIdx.x & 31, ty = threadIdx.x >> 5;
  int c0 = blockIdx.x*32, r0 = blockIdx.y*32;
  #pragma unroll
  for(int j=0;j<4;j++)
    t[ty+8*j][tx] = src[(size_t)(r0+ty+8*j)*W + c0+tx];
  __syncthreads();
  #pragma unroll
  for(int j=0;j<4;j++){
    float v = t[tx][ty+8*j];
    __nv_bfloat16 hi = __float2bfloat16(v);
    __nv_bfloat16 lo = __float2bfloat16(v - __bfloat162float(hi));
    size_t o = (size_t)(c0+ty+8*j)*NN + r0 + tx;
    dH[o] = hi; dL[o] = lo;
  }
}

// ---------------- K5: W[n,j4] = sum_d E[n,d]*wp[d,j4] (float4) ----------------
__global__ void __launch_bounds__(256) k_wcombine(const float* __restrict__ E,
                                                  const float* __restrict__ wp,
                                                  int J, int which){
  float* out = which ? g_Wu : g_Wg;
  int j  = (blockIdx.x*256 + threadIdx.x)*4;
  int n0 = blockIdx.y*32;
  float4 w[DEMB];
  #pragma unroll
  for(int d=0; d<DEMB; d++) w[d] = *(const float4*)(wp + (size_t)d*J + j);
  __shared__ float Es[32*DEMB];
  for(int t=threadIdx.x; t<32*DEMB; t+=256) Es[t] = E[n0*DEMB + t];
  __syncthreads();
  #pragma unroll 2
  for(int nn=0; nn<32; nn++){
    float4 a = make_float4(0.f,0.f,0.f,0.f);
    #pragma unroll
    for(int d=0; d<DEMB; d++){
      float e = Es[nn*DEMB+d];
      a.x += e*w[d].x; a.y += e*w[d].y; a.z += e*w[d].z; a.w += e*w[d].w;
    }
    *(float4*)(out + (size_t)(n0+nn)*J + j) = a;
  }
}

// ---------------- HMMA bf16x3 GEMM, 4-stage cp.async pipeline ----------------
#define PITCH    48                      // bytes per 16-col bf16 row
#define TILE_B   (128*PITCH)             // 6144
#define STAGE_B  (4*TILE_B)              // 24576: Ahi, Alo, Bhi, Blo
#define NSTAGE   4
#define SM_TOT   (NSTAGE*STAGE_B)        // 98304

template<int MODE, int WRITE_T>
__global__ void __launch_bounds__(256,2) mma_gemm(int cId, int dId, int Ncols,
                                                  int bHiId, int tHiId){
  extern __shared__ char smem[];
  float*       C = pickOut(cId);
  const float* D = pickIn(dId);
  const __nv_bfloat16* Bh = pickBF(bHiId);
  const __nv_bfloat16* Bl = pickBF(bHiId+1);
  const uint32_t sb = smem_u32(smem);
  const int tid = threadIdx.x, wid = tid >> 5, lane = tid & 31;
  const int warpM = wid & 3, warpN = wid >> 2;
  const size_t row0 = (size_t)blockIdx.y * 128;
  const size_t n0   = (size_t)blockIdx.x * 128;

  const int ldrow = tid >> 1, ldh = tid & 1;     // cp.async mapping

  float acc[2][8][4];
  #pragma unroll
  for(int m=0;m<2;m++)
    #pragma unroll
    for(int n=0;n<8;n++)
      #pragma unroll
      for(int q=0;q<4;q++) acc[m][n][q] = 0.f;

  auto issue = [&](int c){
    const size_t kb = (size_t)c * 16;
    const uint32_t bo = sb + (uint32_t)(c & 3) * STAGE_B;
    const uint32_t so = (uint32_t)(ldrow*PITCH + ldh*16);
    size_t gA = (row0 + ldrow)*(size_t)NN + kb + ldh*8;
    size_t gB = (n0   + ldrow)*(size_t)NN + kb + ldh*8;
    cp16(bo + 0*TILE_B + so, g_Shi + gA);
    cp16(bo + 1*TILE_B + so, g_Slo + gA);
    cp16(bo + 2*TILE_B + so, Bh + gB);
    cp16(bo + 3*TILE_B + so, Bl + gB);
    cp_commit();
  };

  issue(0); issue(1); issue(2);

  const uint32_t aoff = (uint32_t)((warpM*32 + (lane & 15))*PITCH + (lane >> 4)*16);
  const uint32_t boff = (uint32_t)((warpN*64 + ((lane >> 4) & 1)*8 + (lane & 7))*PITCH
                                   + ((lane >> 3) & 1)*16);

  #pragma unroll 2
  for(int c=0; c<128; c++){
    if(c <= 125)      asm volatile("cp.async.wait_group 2;" ::: "memory");
    else if(c == 126) asm volatile("cp.async.wait_group 1;" ::: "memory");
    else              asm volatile("cp.async.wait_group 0;" ::: "memory");
    __syncthreads();
    if(c + 3 < 128) issue(c+3);

    const uint32_t bo = sb + (uint32_t)(c & 3) * STAGE_B;
    uint32_t afH[2][4], afL[2][4];
    #pragma unroll
    for(int mt=0; mt<2; mt++){
      uint32_t ad = bo + aoff + (uint32_t)(mt*16*PITCH);
      ldsm_x4(afH[mt], ad);
      ldsm_x4(afL[mt], ad + TILE_B);
    }
    #pragma unroll
    for(int ntp=0; ntp<4; ntp++){
      uint32_t bd = bo + 2*TILE_B + boff + (uint32_t)(ntp*16*PITCH);
      uint32_t bH[4], bL[4];
      ldsm_x4(bH, bd);
      ldsm_x4(bL, bd + TILE_B);
      #pragma unroll
      for(int mt=0; mt<2; mt++){
        mma16816(acc[mt][2*ntp],   afH[mt], bH);
        mma16816(acc[mt][2*ntp+1], afH[mt], bH+2);
        mma16816(acc[mt][2*ntp],   afH[mt], bL);
        mma16816(acc[mt][2*ntp+1], afH[mt], bL+2);
        mma16816(acc[mt][2*ntp],   afL[mt], bH);
        mma16816(acc[mt][2*ntp+1], afL[mt], bH+2);
      }
    }
  }

  // ---------------- epilogue ----------------
  const int g = lane >> 2, tg = lane & 3;
  #pragma unroll
  for(int mt=0; mt<2; mt++){
    size_t r0g = row0 + warpM*32 + mt*16 + g;
    #pragma unroll
    for(int nt=0; nt<8; nt++){
      size_t col = n0 + warpN*64 + nt*8 + tg*2;
      size_t o0 = r0g      *(size_t)Ncols + col;
      size_t o1 = (r0g + 8)*(size_t)Ncols + col;
      float2 v0 = make_float2(acc[mt][nt][0], acc[mt][nt][1]);
      float2 v1 = make_float2(acc[mt][nt][2], acc[mt][nt][3]);
      if(MODE == 1){
        float2 d0 = *(const float2*)(D + o0);
        float2 d1 = *(const float2*)(D + o1);
        v0.x = 2.f*v0.x - d0.x; v0.y = 2.f*v0.y - d0.y;
        v1.x = 2.f*v1.x - d1.x; v1.y = 2.f*v1.y - d1.y;
      }
      *(float2*)(C + o0) = v0;
      *(float2*)(C + o1) = v1;
    }
  }

  if(WRITE_T){
    __nv_bfloat16* TH = pickBF(tHiId);
    __nv_bfloat16* TL = pickBF(tHiId+1);
    float* tile = (float*)smem;          // [128][132]
    __syncthreads();                     // pipeline smem dead
    #pragma unroll
    for(int mt=0; mt<2; mt++){
      int rr = warpM*32 + mt*16 + g;
      #pragma unroll
      for(int nt=0; nt<8; nt++){
        int cc = warpN*64 + nt*8 + tg*2;
        tile[rr*132 + cc]     = acc[mt][nt][0];
        tile[rr*132 + cc + 1] = acc[mt][nt][1];
        tile[(rr+8)*132 + cc]     = acc[mt][nt][2];
        tile[(rr+8)*132 + cc + 1] = acc[mt][nt][3];
      }
    }
    __syncthreads();
    int c0 = tid >> 1, half = tid & 1;
    size_t baseO = (size_t)(n0 + c0)*NN + row0 + half*64;
    #pragma unroll
    for(int ch=0; ch<8; ch++){
      __nv_bfloat16 hb[8], lb8[8];
      #pragma unroll
      for(int e=0; e<8; e++){
        float v = tile[(half*64 + ch*8 + e)*132 + c0];
        __nv_bfloat16 hi = __float2bfloat16(v);
        hb[e] = hi;
        lb8[e] = __float2bfloat16(v - __bfloat162float(hi));
      }
      *(uint4*)(TH + baseO + ch*8) = *(uint4*)hb;
      *(uint4*)(TL + baseO + ch*8) = *(uint4*)lb8;
    }
  }
}

// ---------------- K6: gate final ----------------
__global__ void __launch_bounds__(256) k_gate_final(const float* __restrict__ E,
                                                    const float* __restrict__ gbp,
                                                    const float* __restrict__ lw,
                                                    const float* __restrict__ lb){
  __shared__ float smA[128*68];
  __shared__ float ysig[BATCH*CTOT];
  __shared__ float bias[CTOT];
  int n = blockIdx.x, tid = threadIdx.x;

  float* Xs = smA;
  for(int t=tid; t<512; t+=256){
    ((float4*)Xs)[t]        = ((const float4*)(g_IAS + (size_t)n*BC))[t];
    ((float4*)(Xs+2048))[t] = ((const float4*)(g_XG1 + (size_t)n*BC))[t];
    ((float4*)(Xs+4096))[t] = ((const float4*)(g_XG2 + (size_t)n*BC))[t];
  }
  if(tid < CTOT){
    float b = 0.f;
    #pragma unroll
    for(int d=0; d<DEMB; d++) b += E[n*DEMB + d]*gbp[d*CTOT + tid];
    bias[tid] = b;
  }
  __syncthreads();

  int oq = (tid & 31)*4;
  int b0 = (tid >> 5)*2, b1 = b0 + 1;
  float acc[2][4];
  #pragma unroll
  for(int q=0;q<4;q++){ acc[0][q] = bias[oq+q]; acc[1][q] = bias[oq+q]; }

  const float* W = g_Wg + (size_t)n*JG + oq;
  #pragma unroll
  for(int k=0; k<3; k++){
    const float* Xk0 = Xs + k*2048 + b0*CTOT;
    const float* Xk1 = Xs + k*2048 + b1*CTOT;
    const float* Wk  = W + (size_t)k*128*CTOT;
    #pragma unroll 8
    for(int i=0; i<128; i++){
      float4 w4 = *(const float4*)(Wk + (size_t)i*CTOT);
      float x0 = Xk0[i], x1 = Xk1[i];
      acc[0][0] += x0*w4.x; acc[0][1] += x0*w4.y; acc[0][2] += x0*w4.z; acc[0][3] += x0*w4.w;
      acc[1][0] += x1*w4.x; acc[1][1] += x1*w4.y; acc[1][2] += x1*w4.z; acc[1][3] += x1*w4.w;
    }
  }
  #pragma unroll
  for(int bb=0; bb<2; bb++){
    float4 v;
    v.x = 1.f/(1.f + expf(-acc[bb][0]));
    v.y = 1.f/(1.f + expf(-acc[bb][1]));
    v.z = 1.f/(1.f + expf(-acc[bb][2]));
    v.w = 1.f/(1.f + expf(-acc[bb][3]));
    *(float4*)(ysig + (b0+bb)*CTOT + oq) = v;
  }
  __syncthreads();

  float* lwT = smA;
  for(int t=tid; t<CO*CTOT; t+=256){ int c = t>>7, oo = t&127; lwT[oo*68 + c] = lw[t]; }
  __syncthreads();

  int c4  = (tid & 15)*4;
  int bg  = tid >> 4;
  float acc2[4];
  #pragma unroll
  for(int q=0;q<4;q++) acc2[q] = lb[c4+q];
  const float* Ys = ysig + bg*CTOT;
  #pragma unroll 8
  for(int o2=0; o2<CTOT; o2++){
    float4 w4 = *(const float4*)(lwT + o2*68 + c4);
    float y = Ys[o2];
    acc2[0] += y*w4.x; acc2[1] += y*w4.y; acc2[2] += y*w4.z; acc2[3] += y*w4.w;
  }
  *(float4*)(g_Z + (size_t)n*BZ + bg*CO + c4) = make_float4(acc2[0],acc2[1],acc2[2],acc2[3]);
}

// ---------------- K9: upd final ----------------
__global__ void __launch_bounds__(256) k_upd_final(const float* __restrict__ E,
                                                   const float* __restrict__ ubp,
                                                   float* __restrict__ out){
  __shared__ float Xs[3*1024];
  __shared__ float Zs[3*1024];
  __shared__ float bias[CO];
  int n = blockIdx.x, tid = threadIdx.x;
  {
    const float* s0 = g_IAS + (size_t)n*BC;
    const float* s1 = g_XG1 + (size_t)n*BC;
    const float* s2 = g_XG2 + (size_t)n*BC;
    int b = tid >> 4, f = (tid & 15)*4;
    ((float4*)(Xs       ))[tid] = *(const float4*)(s0 + b*CTOT + f);
    ((float4*)(Xs + 1024))[tid] = *(const float4*)(s1 + b*CTOT + f);
    ((float4*)(Xs + 2048))[tid] = *(const float4*)(s2 + b*CTOT + f);
    ((float4*)(Zs       ))[tid] = ((const float4*)(g_Z   + (size_t)n*BZ))[tid];
    ((float4*)(Zs + 1024))[tid] = ((const float4*)(g_ZG1 + (size_t)n*BZ))[tid];
    ((float4*)(Zs + 2048))[tid] = ((const float4*)(g_ZG2 + (size_t)n*BZ))[tid];
  }
  if(tid < CO){
    float b = 0.f;
    #pragma unroll
    for(int d=0; d<DEMB; d++) b += E[n*DEMB + d]*ubp[d*CO + tid];
    bias[tid] = b;
  }
  __syncthreads();

  int oq = (tid & 15)*4;
  int bg = tid >> 4;
  float acc[4];
  #pragma unroll
  for(int q=0;q<4;q++) acc[q] = bias[oq+q];

  const float* W = g_Wu + (size_t)n*JU + oq;
  #pragma unroll
  for(int k=0; k<3; k++){
    const float* Xk = Xs + k*1024 + bg*CO;
    const float* Zk = Zs + k*1024 + bg*CO;
    const float* Wk = W + (size_t)k*128*CO;
    #pragma unroll 8
    for(int i=0; i<64; i++){
      float4 w4 = *(const float4*)(Wk + (size_t)i*CO);
      float x = Xk[i];
      acc[0] += x*w4.x; acc[1] += x*w4.y; acc[2] += x*w4.z; acc[3] += x*w4.w;
    }
    const float* Wk2 = Wk + (size_t)64*CO;
    #pragma unroll 8
    for(int i=0; i<64; i++){
      float4 w4 = *(const float4*)(Wk2 + (size_t)i*CO);
      float z = Zk[i];
      acc[0] += z*w4.x; acc[1] += z*w4.y; acc[2] += z*w4.z; acc[3] += z*w4.w;
    }
  }
  float4 v = make_float4(tanhf(acc[0]), tanhf(acc[1]), tanhf(acc[2]), tanhf(acc[3]));
  *(float4*)(out + ((size_t)bg*NN + n)*CO + oq) = v;
}

// ---------------- launch ----------------
extern "C" void kernel_launch(void* const* d_in, const int* in_sizes, int n_in,
                              void* d_out, int out_size){
  (void)in_sizes; (void)n_in; (void)out_size;
  const float* x   = (const float*)d_in[0];
  const float* st  = (const float*)d_in[1];
  const float* E   = (const float*)d_in[2];
  const float* gwp = (const float*)d_in[3];
  const float* gbp = (const float*)d_in[4];
  const float* uwp = (const float*)d_in[5];
  const float* ubp = (const float*)d_in[6];
  const float* lw  = (const float*)d_in[7];
  const float* lb  = (const float*)d_in[8];
  float* out = (float*)d_out;

  static cudaStream_t sSide = 0;
  static cudaEvent_t evFork = 0, evJoin = 0;
  static int init_done = 0;
  if(!init_done){
    cudaFuncSetAttribute(mma_gemm<0,1>, cudaFuncAttributeMaxDynamicSharedMemorySize, SM_TOT);
    cudaFuncSetAttribute(mma_gemm<1,0>, cudaFuncAttributeMaxDynamicSharedMemorySize, SM_TOT);
    cudaStreamCreateWithFlags(&sSide, cudaStreamNonBlocking);
    cudaEventCreateWithFlags(&evFork, cudaEventDisableTiming);
    cudaEventCreateWithFlags(&evJoin, cudaEventDisableTiming);
    init_done = 1;
  }

  // launches 1-3 (main/legacy stream)
  k_supports<<<NN, 256>>>(E);
  k_pack<<<(NN*BC/4)/256, 256>>>(x, st);
  k_cvtT<<<dim3(BC/32, NN/32), 256>>>(0, BC, 0);                        // IAS -> Ta

  // launch 4 (profiled): big GEMM1
  mma_gemm<0,1><<<dim3(BC/128, NN/128), 256, SM_TOT>>>(1, 0, BC, 0, 2); // XG1; T->Tb

  // fork: wcombine runs on side stream, overlapping GEMM2
  cudaEventRecord(evFork, 0);
  cudaStreamWaitEvent(sSide, evFork, 0);
  k_wcombine<<<dim3(JG/1024, NN/32), 256, 0, sSide>>>(E, gwp, JG, 0);
  k_wcombine<<<dim3(JU/1024, NN/32), 256, 0, sSide>>>(E, uwp, JU, 1);
  cudaEventRecord(evJoin, sSide);

  mma_gemm<1,0><<<dim3(BC/128, NN/128), 256, SM_TOT>>>(2, 0, BC, 2, 0); // XG2 = 2S@XG1-IAS

  cudaStreamWaitEvent(0, evJoin, 0);                                    // need g_Wg
  k_gate_final<<<NN, 256>>>(E, gbp, lw, lb);                            // -> g_Z

  k_cvtT<<<dim3(BZ/32, NN/32), 256>>>(3, BZ, 0);                        // Z -> Ta
  mma_gemm<0,1><<<dim3(BZ/128, NN/128), 256, SM_TOT>>>(4, 3, BZ, 0, 2); // ZG1; T->Tb
  mma_gemm<1,0><<<dim3(BZ/128, NN/128), 256, SM_TOT>>>(5, 3, BZ, 2, 0); // ZG2 = 2S@ZG1-Z

  k_upd_final<<<NN, 256>>>(E, ubp, out);                                // -> hc
}

// round 6
// speedup vs baseline: 1.9828x; 1.0180x over previous
#include <cuda_runtime.h>
#include <cuda_bf16.h>
#include <math.h>
#include <stdint.h>

#define NN    2048
#define BATCH 16
#define DEMB  10
#define CTOT  128
#define CO    64
#define BC    (BATCH*CTOT)   // 2048
#define BZ    (BATCH*CO)     // 1024
#define KC    (3*CTOT)       // 384
#define JG    (KC*CTOT)      // 49152
#define JU    (KC*CO)        // 24576

// ---------------- device scratch ----------------
__device__ float g_IAS[(size_t)NN*BC];
__device__ float g_XG1[(size_t)NN*BC];
__device__ float g_XG2[(size_t)NN*BC];
__device__ float g_Z  [(size_t)NN*BZ];
__device__ float g_ZG1[(size_t)NN*BZ];
__device__ float g_ZG2[(size_t)NN*BZ];
__device__ float g_Wg [(size_t)NN*JG];
__device__ float g_Wu [(size_t)NN*JU];
__device__ __align__(256) __nv_bfloat16 g_Shi[(size_t)NN*NN];
__device__ __align__(256) __nv_bfloat16 g_Slo[(size_t)NN*NN];
__device__ __align__(256) __nv_bfloat16 g_TaH[(size_t)NN*NN];
__device__ __align__(256) __nv_bfloat16 g_TaL[(size_t)NN*NN];
__device__ __align__(256) __nv_bfloat16 g_TbH[(size_t)NN*NN];
__device__ __align__(256) __nv_bfloat16 g_TbL[(size_t)NN*NN];

// ---------------- pickers ----------------
__device__ __forceinline__ const float* pickIn(int id){
  switch(id){ case 0: return g_IAS; case 1: return g_XG1; case 2: return g_XG2;
              case 3: return g_Z;   case 4: return g_ZG1; }
  return g_IAS;
}
__device__ __forceinline__ float* pickOut(int id){
  switch(id){ case 1: return g_XG1; case 2: return g_XG2;
              case 4: return g_ZG1; case 5: return g_ZG2; }
  return g_XG1;
}
__device__ __forceinline__ __nv_bfloat16* pickBF(int id){
  switch(id){ case 0: return g_TaH; case 1: return g_TaL;
              case 2: return g_TbH; case 3: return g_TbL; }
  return g_TaH;
}

// ---------------- warp reductions ----------------
__device__ __forceinline__ float warpMax(float v){
  #pragma unroll
  for(int o=16;o;o>>=1) v = fmaxf(v, __shfl_xor_sync(0xffffffffu, v, o));
  return v;
}
__device__ __forceinline__ float warpSum(float v){
  #pragma unroll
  for(int o=16;o;o>>=1) v += __shfl_xor_sync(0xffffffffu, v, o);
  return v;
}

// ---------------- PTX helpers ----------------
__device__ __forceinline__ uint32_t smem_u32(const void* p){
  uint32_t a;
  asm("{ .reg .u64 t; cvta.to.shared.u64 t, %1; cvt.u32.u64 %0, t; }" : "=r"(a) : "l"(p));
  return a;
}
__device__ __forceinline__ void cp16(uint32_t s, const void* g){
  asm volatile("cp.async.cg.shared.global [%0], [%1], 16;" :: "r"(s), "l"(g) : "memory");
}
__device__ __forceinline__ void cp_commit(){ asm volatile("cp.async.commit_group;" ::: "memory"); }
__device__ __forceinline__ void ldsm_x4(uint32_t* r, uint32_t a){
  asm volatile("ldmatrix.sync.aligned.m8n8.x4.shared.b16 {%0,%1,%2,%3}, [%4];"
    : "=r"(r[0]),"=r"(r[1]),"=r"(r[2]),"=r"(r[3]) : "r"(a));
}
__device__ __forceinline__ void mma16816(float* d, const uint32_t* a, const uint32_t* b){
  asm volatile("mma.sync.aligned.m16n8k16.row.col.f32.bf16.bf16.f32 "
    "{%0,%1,%2,%3}, {%4,%5,%6,%7}, {%8,%9}, {%0,%1,%2,%3};"
    : "+f"(d[0]),"+f"(d[1]),"+f"(d[2]),"+f"(d[3])
    : "r"(a[0]),"r"(a[1]),"r"(a[2]),"r"(a[3]), "r"(b[0]),"r"(b[1]));
}

// ---------------- K1: S row softmax -> bf16 hi/lo ----------------
__global__ void __launch_bounds__(256) k_supports(const float* __restrict__ E){
  __shared__ float sh[8];
  __shared__ float bcast;
  int row = blockIdx.x, tid = threadIdx.x;
  float Er[DEMB];
  #pragma unroll
  for(int d=0; d<DEMB; d++) Er[d] = E[row*DEMB + d];
  float a[8], m = -1e30f;
  #pragma unroll
  for(int q=0; q<8; q++){
    int col = tid + q*256;
    const float* Ec = E + (size_t)col*DEMB;
    float s = 0.f;
    #pragma unroll
    for(int d=0; d<DEMB; d++) s += Er[d]*Ec[d];
    s = fmaxf(s, 0.f);
    a[q] = s; m = fmaxf(m, s);
  }
  m = warpMax(m);
  if((tid&31)==0) sh[tid>>5] = m;
  __syncthreads();
  if(tid<32){ float t = (tid<8)? sh[tid] : -1e30f; t = warpMax(t); if(tid==0) bcast = t; }
  __syncthreads();
  m = bcast;
  float ssum = 0.f;
  #pragma unroll
  for(int q=0; q<8; q++){ a[q] = expf(a[q]-m); ssum += a[q]; }
  ssum = warpSum(ssum);
  __syncthreads();
  if((tid&31)==0) sh[tid>>5] = ssum;
  __syncthreads();
  if(tid<32){ float t = (tid<8)? sh[tid] : 0.f; t = warpSum(t); if(tid==0) bcast = t; }
  __syncthreads();
  float inv = 1.f/bcast;
  #pragma unroll
  for(int q=0; q<8; q++){
    float v = a[q]*inv;
    __nv_bfloat16 hi = __float2bfloat16(v);
    __nv_bfloat16 lo = __float2bfloat16(v - __bfloat162float(hi));
    size_t o = (size_t)row*NN + tid + q*256;
    g_Shi[o] = hi; g_Slo[o] = lo;
  }
}

// ---------------- K2: pack IAS ----------------
__global__ void __launch_bounds__(256) k_pack(const float* __restrict__ x,
                                              const float* __restrict__ st){
  int t = blockIdx.x*256 + threadIdx.x;
  int e = t*4;
  int n = e >> 11;
  int r = e & 2047;
  int b = r >> 7;
  int c = r & 127;
  float4 v;
  if (c < 64) v = *(const float4*)(x  + ((size_t)b*NN + n)*64 + c);
  else        v = *(const float4*)(st + ((size_t)b*NN + n)*64 + (c-64));
  *(float4*)(g_IAS + e) = v;
}

// -------- convert+transpose fp32 [2048 x W] -> bf16 hi/lo [W x 2048] --------
__global__ void __launch_bounds__(256) k_cvtT(int srcId, int W, int dstHi){
  const float* src = pickIn(srcId);
  __nv_bfloat16* dH = pickBF(dstHi);
  __nv_bfloat16* dL = pickBF(dstHi+1);
  __shared__ float t[32][33];
  int tx = threadIdx.x & 31, ty = threadIdx.x >> 5;
  int c0 = blockIdx.x*32, r0 = blockIdx.y*32;
  #pragma unroll
  for(int j=0;j<4;j++)
    t[ty+8*j][tx] = src[(size_t)(r0+ty+8*j)*W + c0+tx];
  __syncthreads();
  #pragma unroll
  for(int j=0;j<4;j++){
    float v = t[tx][ty+8*j];
    __nv_bfloat16 hi = __float2bfloat16(v);
    __nv_bfloat16 lo = __float2bfloat16(v - __bfloat162float(hi));
    size_t o = (size_t)(c0+ty+8*j)*NN + r0 + tx;
    dH[o] = hi; dL[o] = lo;
  }
}

// ---------------- K5: wcombine (float4) ----------------
__global__ void __launch_bounds__(256) k_wcombine(const float* __restrict__ E,
                                                  const float* __restrict__ wp,
                                                  int J, int which){
  float* out = which ? g_Wu : g_Wg;
  int j  = (blockIdx.x*256 + threadIdx.x)*4;
  int n0 = blockIdx.y*32;
  float4 w[DEMB];
  #pragma unroll
  for(int d=0; d<DEMB; d++) w[d] = *(const float4*)(wp + (size_t)d*J + j);
  __shared__ float Es[32*DEMB];
  for(int t=threadIdx.x; t<32*DEMB; t+=256) Es[t] = E[n0*DEMB + t];
  __syncthreads();
  #pragma unroll 2
  for(int nn=0; nn<32; nn++){
    float4 a = make_float4(0.f,0.f,0.f,0.f);
    #pragma unroll
    for(int d=0; d<DEMB; d++){
      float e = Es[nn*DEMB+d];
      a.x += e*w[d].x; a.y += e*w[d].y; a.z += e*w[d].z; a.w += e*w[d].w;
    }
    *(float4*)(out + (size_t)(n0+nn)*J + j) = a;
  }
}

// ---------------- HMMA bf16x3 GEMM, 4-stage cp.async pipeline ----------------
// TM = CTA M-tile (128 or 64); N-tile fixed 128; K-chunk 16.
#define PITCH    48

template<int MODE, int WRITE_T, int TM>
__global__ void __launch_bounds__(256,2) mma_gemm(int cId, int dId, int Ncols,
                                                  int bHiId, int tHiId){
  constexpr int WM   = (TM == 128) ? 4 : 2;     // warps along M
  constexpr int WN   = 8 / WM;                  // warps along N
  constexpr int NT   = (128 / WN) / 8;          // 8x8 n-tiles per warp: 8 or 4
  constexpr int NTP  = NT / 2;
  constexpr int A_T  = TM * PITCH;              // A tile bytes
  constexpr int B_T  = 128 * PITCH;
  constexpr int STG  = 2*A_T + 2*B_T;           // stage bytes
  constexpr int NTRANS = (2*TM + 2*128) * 2;    // 16B transfers per stage

  extern __shared__ char smem[];
  float*       C = pickOut(cId);
  const float* D = pickIn(dId);
  const __nv_bfloat16* Bh = pickBF(bHiId);
  const __nv_bfloat16* Bl = pickBF(bHiId+1);
  const uint32_t sb = smem_u32(smem);
  const int tid = threadIdx.x, wid = tid >> 5, lane = tid & 31;
  const int warpM = wid % WM, warpN = wid / WM;
  const size_t row0 = (size_t)blockIdx.y * TM;
  const size_t n0   = (size_t)blockIdx.x * 128;

  float acc[2][NT][4];
  #pragma unroll
  for(int m=0;m<2;m++)
    #pragma unroll
    for(int n=0;n<NT;n++)
      #pragma unroll
      for(int q=0;q<4;q++) acc[m][n][q] = 0.f;

  auto issue = [&](int c){
    const size_t kb = (size_t)c * 16;
    const uint32_t bo = sb + (uint32_t)(c & 3) * STG;
    #pragma unroll
    for(int u = 0; u < NTRANS/256; u++){
      int e  = tid + u*256;
      int h  = e & 1;
      int rr = e >> 1;
      uint32_t so; const __nv_bfloat16* gp;
      if(rr < TM){                 so = bo + rr*PITCH + h*16;
                                   gp = g_Shi + (row0 + rr)*(size_t)NN + kb + h*8; }
      else if(rr < 2*TM){          int r = rr - TM;
                                   so = bo + A_T + r*PITCH + h*16;
                                   gp = g_Slo + (row0 + r)*(size_t)NN + kb + h*8; }
      else if(rr < 2*TM + 128){    int r = rr - 2*TM;
                                   so = bo + 2*A_T + r*PITCH + h*16;
                                   gp = Bh + (n0 + r)*(size_t)NN + kb + h*8; }
      else{                        int r = rr - 2*TM - 128;
                                   so = bo + 2*A_T + B_T + r*PITCH + h*16;
                                   gp = Bl + (n0 + r)*(size_t)NN + kb + h*8; }
      cp16(so, gp);
    }
    cp_commit();
  };

  issue(0); issue(1); issue(2);

  const uint32_t aoff = (uint32_t)((warpM*32 + (lane & 15))*PITCH + (lane >> 4)*16);
  const uint32_t boff = (uint32_t)(2*A_T + (warpN*(NT*8) + ((lane >> 4) & 1)*8 + (lane & 7))*PITCH
                                   + ((lane >> 3) & 1)*16);

  for(int c=0; c<128; c++){
    if(c <= 125)      asm volatile("cp.async.wait_group 2;" ::: "memory");
    else if(c == 126) asm volatile("cp.async.wait_group 1;" ::: "memory");
    else              asm volatile("cp.async.wait_group 0;" ::: "memory");
    __syncthreads();
    if(c + 3 < 128) issue(c+3);

    const uint32_t bo = sb + (uint32_t)(c & 3) * STG;
    uint32_t afH[2][4], afL[2][4];
    #pragma unroll
    for(int mt=0; mt<2; mt++){
      uint32_t ad = bo + aoff + (uint32_t)(mt*16*PITCH);
      ldsm_x4(afH[mt], ad);
      ldsm_x4(afL[mt], ad + A_T);
    }
    #pragma unroll
    for(int ntp=0; ntp<NTP; ntp++){
      uint32_t bd = bo + boff + (uint32_t)(ntp*16*PITCH);
      uint32_t bH[4], bL[4];
      ldsm_x4(bH, bd);
      ldsm_x4(bL, bd + B_T);
      // ILP-ordered: dependent accumulator reuse at distance 4
      mma16816(acc[0][2*ntp],   afH[0], bH);
      mma16816(acc[1][2*ntp],   afH[1], bH);
      mma16816(acc[0][2*ntp+1], afH[0], bH+2);
      mma16816(acc[1][2*ntp+1], afH[1], bH+2);
      mma16816(acc[0][2*ntp],   afH[0], bL);
      mma16816(acc[1][2*ntp],   afH[1], bL);
      mma16816(acc[0][2*ntp+1], afH[0], bL+2);
      mma16816(acc[1][2*ntp+1], afH[1], bL+2);
      mma16816(acc[0][2*ntp],   afL[0], bH);
      mma16816(acc[1][2*ntp],   afL[1], bH);
      mma16816(acc[0][2*ntp+1], afL[0], bH+2);
      mma16816(acc[1][2*ntp+1], afL[1], bH+2);
    }
  }

  // ---------------- epilogue ----------------
  const int g = lane >> 2, tg = lane & 3;
  #pragma unroll
  for(int mt=0; mt<2; mt++){
    size_t r0g = row0 + warpM*32 + mt*16 + g;
    #pragma unroll
    for(int nt=0; nt<NT; nt++){
      size_t col = n0 + warpN*(NT*8) + nt*8 + tg*2;
      size_t o0 = r0g      *(size_t)Ncols + col;
      size_t o1 = (r0g + 8)*(size_t)Ncols + col;
      float2 v0 = make_float2(acc[mt][nt][0], acc[mt][nt][1]);
      float2 v1 = make_float2(acc[mt][nt][2], acc[mt][nt][3]);
      if(MODE == 1){
        float2 d0 = *(const float2*)(D + o0);
        float2 d1 = *(const float2*)(D + o1);
        v0.x = 2.f*v0.x - d0.x; v0.y = 2.f*v0.y - d0.y;
        v1.x = 2.f*v1.x - d1.x; v1.y = 2.f*v1.y - d1.y;
      }
      *(float2*)(C + o0) = v0;
      *(float2*)(C + o1) = v1;
    }
  }

  if(WRITE_T){
    __nv_bfloat16* TH = pickBF(tHiId);
    __nv_bfloat16* TL = pickBF(tHiId+1);
    float* tile = (float*)smem;          // [TM][132]
    __syncthreads();
    #pragma unroll
    for(int mt=0; mt<2; mt++){
      int rr = warpM*32 + mt*16 + g;
      #pragma unroll
      for(int nt=0; nt<NT; nt++){
        int cc = warpN*(NT*8) + nt*8 + tg*2;
        tile[rr*132 + cc]     = acc[mt][nt][0];
        tile[rr*132 + cc + 1] = acc[mt][nt][1];
        tile[(rr+8)*132 + cc]     = acc[mt][nt][2];
        tile[(rr+8)*132 + cc + 1] = acc[mt][nt][3];
      }
    }
    __syncthreads();
    int c0 = tid >> 1, half = tid & 1;
    size_t baseO = (size_t)(n0 + c0)*NN + row0 + half*(TM/2);
    #pragma unroll
    for(int ch=0; ch<TM/16; ch++){
      __nv_bfloat16 hb[8], lb8[8];
      #pragma unroll
      for(int e=0; e<8; e++){
        float v = tile[(half*(TM/2) + ch*8 + e)*132 + c0];
        __nv_bfloat16 hi = __float2bfloat16(v);
        hb[e] = hi;
        lb8[e] = __float2bfloat16(v - __bfloat162float(hi));
      }
      *(uint4*)(TH + baseO + ch*8) = *(uint4*)hb;
      *(uint4*)(TL + baseO + ch*8) = *(uint4*)lb8;
    }
  }
}

#define SM_128  (2*(128*PITCH) + 2*(128*PITCH))*4   // 98304
#define SM_64   (2*(64*PITCH) + 2*(128*PITCH))*4    // 73728

// ---------------- K6: gate final ----------------
__global__ void __launch_bounds__(256) k_gate_final(const float* __restrict__ E,
                                                    const float* __restrict__ gbp,
                                                    const float* __restrict__ lw,
                                                    const float* __restrict__ lb){
  __shared__ float smA[128*68];
  __shared__ float ysig[BATCH*CTOT];
  __shared__ float bias[CTOT];
  int n = blockIdx.x, tid = threadIdx.x;

  float* Xs = smA;
  for(int t=tid; t<512; t+=256){
    ((float4*)Xs)[t]        = ((const float4*)(g_IAS + (size_t)n*BC))[t];
    ((float4*)(Xs+2048))[t] = ((const float4*)(g_XG1 + (size_t)n*BC))[t];
    ((float4*)(Xs+4096))[t] = ((const float4*)(g_XG2 + (size_t)n*BC))[t];
  }
  if(tid < CTOT){
    float b = 0.f;
    #pragma unroll
    for(int d=0; d<DEMB; d++) b += E[n*DEMB + d]*gbp[d*CTOT + tid];
    bias[tid] = b;
  }
  __syncthreads();

  int oq = (tid & 31)*4;
  int b0 = (tid >> 5)*2, b1 = b0 + 1;
  float acc[2][4];
  #pragma unroll
  for(int q=0;q<4;q++){ acc[0][q] = bias[oq+q]; acc[1][q] = bias[oq+q]; }

  const float* W = g_Wg + (size_t)n*JG + oq;
  #pragma unroll
  for(int k=0; k<3; k++){
    const float* Xk0 = Xs + k*2048 + b0*CTOT;
    const float* Xk1 = Xs + k*2048 + b1*CTOT;
    const float* Wk  = W + (size_t)k*128*CTOT;
    #pragma unroll 8
    for(int i=0; i<128; i++){
      float4 w4 = *(const float4*)(Wk + (size_t)i*CTOT);
      float x0 = Xk0[i], x1 = Xk1[i];
      acc[0][0] += x0*w4.x; acc[0][1] += x0*w4.y; acc[0][2] += x0*w4.z; acc[0][3] += x0*w4.w;
      acc[1][0] += x1*w4.x; acc[1][1] += x1*w4.y; acc[1][2] += x1*w4.z; acc[1][3] += x1*w4.w;
    }
  }
  #pragma unroll
  for(int bb=0; bb<2; bb++){
    float4 v;
    v.x = 1.f/(1.f + expf(-acc[bb][0]));
    v.y = 1.f/(1.f + expf(-acc[bb][1]));
    v.z = 1.f/(1.f + expf(-acc[bb][2]));
    v.w = 1.f/(1.f + expf(-acc[bb][3]));
    *(float4*)(ysig + (b0+bb)*CTOT + oq) = v;
  }
  __syncthreads();

  float* lwT = smA;
  for(int t=tid; t<CO*CTOT; t+=256){ int c = t>>7, oo = t&127; lwT[oo*68 + c] = lw[t]; }
  __syncthreads();

  int c4  = (tid & 15)*4;
  int bg  = tid >> 4;
  float acc2[4];
  #pragma unroll
  for(int q=0;q<4;q++) acc2[q] = lb[c4+q];
  const float* Ys = ysig + bg*CTOT;
  #pragma unroll 8
  for(int o2=0; o2<CTOT; o2++){
    float4 w4 = *(const float4*)(lwT + o2*68 + c4);
    float y = Ys[o2];
    acc2[0] += y*w4.x; acc2[1] += y*w4.y; acc2[2] += y*w4.z; acc2[3] += y*w4.w;
  }
  *(float4*)(g_Z + (size_t)n*BZ + bg*CO + c4) = make_float4(acc2[0],acc2[1],acc2[2],acc2[3]);
}

// ---------------- K9: upd final ----------------
__global__ void __launch_bounds__(256) k_upd_final(const float* __restrict__ E,
                                                   const float* __restrict__ ubp,
                                                   float* __restrict__ out){
  __shared__ float Xs[3*1024];
  __shared__ float Zs[3*1024];
  __shared__ float bias[CO];
  int n = blockIdx.x, tid = threadIdx.x;
  {
    const float* s0 = g_IAS + (size_t)n*BC;
    const float* s1 = g_XG1 + (size_t)n*BC;
    const float* s2 = g_XG2 + (size_t)n*BC;
    int b = tid >> 4, f = (tid & 15)*4;
    ((float4*)(Xs       ))[tid] = *(const float4*)(s0 + b*CTOT + f);
    ((float4*)(Xs + 1024))[tid] = *(const float4*)(s1 + b*CTOT + f);
    ((float4*)(Xs + 2048))[tid] = *(const float4*)(s2 + b*CTOT + f);
    ((float4*)(Zs       ))[tid] = ((const float4*)(g_Z   + (size_t)n*BZ))[tid];
    ((float4*)(Zs + 1024))[tid] = ((const float4*)(g_ZG1 + (size_t)n*BZ))[tid];
    ((float4*)(Zs + 2048))[tid] = ((const float4*)(g_ZG2 + (size_t)n*BZ))[tid];
  }
  if(tid < CO){
    float b = 0.f;
    #pragma unroll
    for(int d=0; d<DEMB; d++) b += E[n*DEMB + d]*ubp[d*CO + tid];
    bias[tid] = b;
  }
  __syncthreads();

  int oq = (tid & 15)*4;
  int bg = tid >> 4;
  float acc[4];
  #pragma unroll
  for(int q=0;q<4;q++) acc[q] = bias[oq+q];

  const float* W = g_Wu + (size_t)n*JU + oq;
  #pragma unroll
  for(int k=0; k<3; k++){
    const float* Xk = Xs + k*1024 + bg*CO;
    const float* Zk = Zs + k*1024 + bg*CO;
    const float* Wk = W + (size_t)k*128*CO;
    #pragma unroll 8
    for(int i=0; i<64; i++){
      float4 w4 = *(const float4*)(Wk + (size_t)i*CO);
      float x = Xk[i];
      acc[0] += x*w4.x; acc[1] += x*w4.y; acc[2] += x*w4.z; acc[3] += x*w4.w;
    }
    const float* Wk2 = Wk + (size_t)64*CO;
    #pragma unroll 8
    for(int i=0; i<64; i++){
      float4 w4 = *(const float4*)(Wk2 + (size_t)i*CO);
      float z = Zk[i];
      acc[0] += z*w4.x; acc[1] += z*w4.y; acc[2] += z*w4.z; acc[3] += z*w4.w;
    }
  }
  float4 v = make_float4(tanhf(acc[0]), tanhf(acc[1]), tanhf(acc[2]), tanhf(acc[3]));
  *(float4*)(out + ((size_t)bg*NN + n)*CO + oq) = v;
}

// ---------------- launch ----------------
extern "C" void kernel_launch(void* const* d_in, const int* in_sizes, int n_in,
                              void* d_out, int out_size){
  (void)in_sizes; (void)n_in; (void)out_size;
  const float* x   = (const float*)d_in[0];
  const float* st  = (const float*)d_in[1];
  const float* E   = (const float*)d_in[2];
  const float* gwp = (const float*)d_in[3];
  const float* gbp = (const float*)d_in[4];
  const float* uwp = (const float*)d_in[5];
  const float* ubp = (const float*)d_in[6];
  const float* lw  = (const float*)d_in[7];
  const float* lb  = (const float*)d_in[8];
  float* out = (float*)d_out;

  static cudaStream_t sSide = 0;
  static cudaEvent_t evFork = 0, evJoin = 0;
  static int init_done = 0;
  if(!init_done){
    cudaFuncSetAttribute(mma_gemm<0,1,128>, cudaFuncAttributeMaxDynamicSharedMemorySize, SM_128);
    cudaFuncSetAttribute(mma_gemm<1,0,128>, cudaFuncAttributeMaxDynamicSharedMemorySize, SM_128);
    cudaFuncSetAttribute(mma_gemm<0,1,64>,  cudaFuncAttributeMaxDynamicSharedMemorySize, SM_64);
    cudaFuncSetAttribute(mma_gemm<1,0,64>,  cudaFuncAttributeMaxDynamicSharedMemorySize, SM_64);
    cudaStreamCreateWithFlags(&sSide, cudaStreamNonBlocking);
    cudaEventCreateWithFlags(&evFork, cudaEventDisableTiming);
    cudaEventCreateWithFlags(&evJoin, cudaEventDisableTiming);
    init_done = 1;
  }

  k_supports<<<NN, 256>>>(E);
  k_pack<<<(NN*BC/4)/256, 256>>>(x, st);
  k_cvtT<<<dim3(BC/32, NN/32), 256>>>(0, BC, 0);                            // IAS -> Ta

  // launch 4 (profiled): big GEMM1
  mma_gemm<0,1,128><<<dim3(BC/128, NN/128), 256, SM_128>>>(1, 0, BC, 0, 2); // XG1; T->Tb

  cudaEventRecord(evFork, 0);
  cudaStreamWaitEvent(sSide, evFork, 0);
  k_wcombine<<<dim3(JG/1024, NN/32), 256, 0, sSide>>>(E, gwp, JG, 0);
  k_wcombine<<<dim3(JU/1024, NN/32), 256, 0, sSide>>>(E, uwp, JU, 1);
  cudaEventRecord(evJoin, sSide);

  mma_gemm<1,0,128><<<dim3(BC/128, NN/128), 256, SM_128>>>(2, 0, BC, 2, 0); // XG2

  cudaStreamWaitEvent(0, evJoin, 0);
  k_gate_final<<<NN, 256>>>(E, gbp, lw, lb);                                // -> g_Z

  k_cvtT<<<dim3(BZ/32, NN/32), 256>>>(3, BZ, 0);                            // Z -> Ta
  mma_gemm<0,1,64><<<dim3(BZ/128, NN/64), 256, SM_64>>>(4, 3, BZ, 0, 2);    // ZG1; T->Tb
  mma_gemm<1,0,64><<<dim3(BZ/128, NN/64), 256, SM_64>>>(5, 3, BZ, 2, 0);    // ZG2

  k_upd_final<<<NN, 256>>>(E, ubp, out);                                    // -> hc
}